// round 15
// baseline (speedup 1.0000x reference)
#include <cuda_runtime.h>
#include <cuda_fp16.h>
#include <math.h>
#include <stdint.h>

// ---------------- problem dims ----------------
#define Bc   2
#define Sc   4096
#define Dc   1024
#define Hc   16
#define NBc  64
#define NB2c 32
#define Rc   4
#define DFFc 4096
#define DHc  64
#define Cc   64
#define NCHc 64
#define BHS  (Bc*Hc*Sc)          // 131072
#define BSD  ((size_t)Bc*Sc*Dc)  // 8388608

// ---------------- workspace (static device memory; no allocations) ----------------
__device__ float  g_ln[BSD];
__device__ __half g_lnh[BSD];
__device__ float  g_qk[BSD];
__device__ float  g_v[BSD];
__device__ __half g_attnh[BSD];
__device__ __half g_ffhh[(size_t)Bc*Sc*DFFc];
__device__ float  g_oall[(size_t)Rc*BHS*DHc];
__device__ float  g_lall[(size_t)Rc*BHS];
__device__ int    g_buckets[(size_t)Rc*BHS];
__device__ int    g_order[(size_t)Rc*BHS];
__device__ __half g_WvT[(size_t)Dc*Dc];
__device__ __half g_WoT[(size_t)Dc*Dc];
__device__ __half g_W1T[(size_t)DFFc*Dc];
__device__ __half g_W2T[(size_t)Dc*DFFc];

// ---------------- packed f32x2 helpers ----------------
__device__ __forceinline__ unsigned long long f32x2_pack(float lo, float hi) {
    unsigned long long r;
    asm("mov.b64 %0, {%1, %2};" : "=l"(r) : "f"(lo), "f"(hi));
    return r;
}
__device__ __forceinline__ unsigned long long f32x2_fma(unsigned long long a,
                                                        unsigned long long b,
                                                        unsigned long long c) {
    unsigned long long d;
    asm("fma.rn.f32x2 %0, %1, %2, %3;" : "=l"(d) : "l"(a), "l"(b), "l"(c));
    return d;
}
__device__ __forceinline__ unsigned long long f32x2_mul(unsigned long long a,
                                                        unsigned long long b) {
    unsigned long long d;
    asm("mul.rn.f32x2 %0, %1, %2;" : "=l"(d) : "l"(a), "l"(b));
    return d;
}
__device__ __forceinline__ void f32x2_unpack(unsigned long long v, float& lo, float& hi) {
    asm("mov.b64 {%0, %1}, %2;" : "=f"(lo), "=f"(hi) : "l"(v));
}

// ---------------- mma / cp.async / ldmatrix helpers ----------------
__device__ __forceinline__ void mma_f16(float c[4],
                                        uint32_t a0, uint32_t a1, uint32_t a2, uint32_t a3,
                                        uint32_t b0, uint32_t b1) {
    asm volatile(
        "mma.sync.aligned.m16n8k16.row.col.f32.f16.f16.f32 "
        "{%0,%1,%2,%3}, {%4,%5,%6,%7}, {%8,%9}, {%0,%1,%2,%3};"
        : "+f"(c[0]), "+f"(c[1]), "+f"(c[2]), "+f"(c[3])
        : "r"(a0), "r"(a1), "r"(a2), "r"(a3), "r"(b0), "r"(b1));
}
__device__ __forceinline__ uint32_t smem_u32(const void* p) {
    uint32_t a;
    asm("{ .reg .u64 t; cvta.to.shared.u64 t, %1; cvt.u32.u64 %0, t; }" : "=r"(a) : "l"(p));
    return a;
}
__device__ __forceinline__ void cp_async16cg(uint32_t dst, const void* src) {
    asm volatile("cp.async.cg.shared.global [%0], [%1], 16;" :: "r"(dst), "l"(src));
}
__device__ __forceinline__ void cp_commit() {
    asm volatile("cp.async.commit_group;" ::: "memory");
}
__device__ __forceinline__ void cp_wait1() {
    asm volatile("cp.async.wait_group 1;" ::: "memory");
}
__device__ __forceinline__ void ldsm_x4(uint32_t& r0, uint32_t& r1, uint32_t& r2, uint32_t& r3,
                                        uint32_t addr) {
    asm volatile("ldmatrix.sync.aligned.m8n8.x4.shared.b16 {%0,%1,%2,%3}, [%4];"
                 : "=r"(r0), "=r"(r1), "=r"(r2), "=r"(r3) : "r"(addr));
}

// ---------------- weight transpose to fp16 ----------------
__global__ void transpose_half_kernel(const float* __restrict__ W, __half* __restrict__ Wt,
                                      int K, int N)
{
    __shared__ float tile[32][33];
    const int bn = blockIdx.x * 32;
    const int bk = blockIdx.y * 32;
    const int tx = threadIdx.x & 31;
    const int ty = threadIdx.x >> 5;
    #pragma unroll
    for (int i = 0; i < 32; i += 8)
        tile[ty + i][tx] = W[(size_t)(bk + ty + i) * N + bn + tx];
    __syncthreads();
    #pragma unroll
    for (int i = 0; i < 32; i += 8)
        Wt[(size_t)(bn + ty + i) * K + bk + tx] = __float2half_rn(tile[tx][ty + i]);
}

// ---------------- layernorm (vectorized float4): fp32 (optional) + fp16 (optional) ----------------
__global__ void ln_kernel(const float* __restrict__ x, const float* __restrict__ g,
                          const float* __restrict__ bb, float* __restrict__ y,
                          __half* __restrict__ yh)
{
    const int row = blockIdx.x;
    const int tid = threadIdx.x;
    const float4 v = ((const float4*)(x + (size_t)row * Dc))[tid];
    float s1 = ((v.x + v.y) + (v.z + v.w));
    float s2 = fmaf(v.x, v.x, fmaf(v.y, v.y, fmaf(v.z, v.z, v.w * v.w)));

    __shared__ float sh1[8], sh2[8];
    const int lane = tid & 31, w = tid >> 5;
    #pragma unroll
    for (int o = 16; o > 0; o >>= 1) {
        s1 += __shfl_xor_sync(~0u, s1, o);
        s2 += __shfl_xor_sync(~0u, s2, o);
    }
    if (lane == 0) { sh1[w] = s1; sh2[w] = s2; }
    __syncthreads();
    if (w == 0) {
        s1 = (lane < 8) ? sh1[lane] : 0.f;
        s2 = (lane < 8) ? sh2[lane] : 0.f;
        #pragma unroll
        for (int o = 4; o > 0; o >>= 1) {
            s1 += __shfl_xor_sync(~0u, s1, o);
            s2 += __shfl_xor_sync(~0u, s2, o);
        }
        if (lane == 0) { sh1[0] = s1; sh2[0] = s2; }
    }
    __syncthreads();
    const float mean = sh1[0] * (1.f / Dc);
    const float var  = sh2[0] * (1.f / Dc) - mean * mean;
    const float inv  = 1.f / sqrtf(var + 1e-5f);

    const float4 gg = ((const float4*)g)[tid];
    const float4 b4 = ((const float4*)bb)[tid];
    float4 o;
    o.x = (v.x - mean) * inv * gg.x + b4.x;
    o.y = (v.y - mean) * inv * gg.y + b4.y;
    o.z = (v.z - mean) * inv * gg.z + b4.z;
    o.w = (v.w - mean) * inv * gg.w + b4.w;
    if (y) ((float4*)(y + (size_t)row * Dc))[tid] = o;
    if (yh) {
        __half2 h0 = __floats2half2_rn(o.x, o.y);
        __half2 h1 = __floats2half2_rn(o.z, o.w);
        uint32_t u0, u1;
        u0 = *(uint32_t*)&h0; u1 = *(uint32_t*)&h1;
        ((uint2*)(yh + (size_t)row * Dc))[tid] = make_uint2(u0, u1);
    }
}

// ---------------- exact fp32 SGEMM (FFMA2), k-tile 16: qk projection ----------------
__global__ void __launch_bounds__(256, 2) sgemm_kernel(
    const float* __restrict__ A, const float* __restrict__ Bm,
    float* __restrict__ Cm, int M, int N, int K)
{
    __shared__ float As[16][128];
    __shared__ float Bs[16][128];
    const int tid  = threadIdx.x;
    const int row0 = blockIdx.y * 128;
    const int col0 = blockIdx.x * 128;
    const int tx = tid & 15;
    const int ty = tid >> 4;

    const int aRow = tid >> 1;
    const int aCol = (tid & 1) << 3;
    const int bRow = tid >> 4;
    const int bCol = (tid & 15) << 3;

    const float* Aptr = A + (size_t)(row0 + aRow) * K + aCol;
    const float* Bptr = Bm + (size_t)bRow * N + col0 + bCol;

    unsigned long long acc2[8][4];
    #pragma unroll
    for (int i = 0; i < 8; i++)
        #pragma unroll
        for (int j = 0; j < 4; j++) acc2[i][j] = 0ull;

    float4 a4[2], b4[2];
    a4[0] = *(const float4*)(Aptr);
    a4[1] = *(const float4*)(Aptr + 4);
    b4[0] = *(const float4*)(Bptr);
    b4[1] = *(const float4*)(Bptr + 4);

    for (int k0 = 0; k0 < K; k0 += 16) {
        #pragma unroll
        for (int q = 0; q < 2; q++) {
            As[aCol + q * 4 + 0][aRow] = a4[q].x;
            As[aCol + q * 4 + 1][aRow] = a4[q].y;
            As[aCol + q * 4 + 2][aRow] = a4[q].z;
            As[aCol + q * 4 + 3][aRow] = a4[q].w;
        }
        *(float4*)(&Bs[bRow][bCol])     = b4[0];
        *(float4*)(&Bs[bRow][bCol + 4]) = b4[1];
        __syncthreads();

        if (k0 + 16 < K) {
            a4[0] = *(const float4*)(Aptr + k0 + 16);
            a4[1] = *(const float4*)(Aptr + k0 + 20);
            b4[0] = *(const float4*)(Bptr + (size_t)(k0 + 16) * N);
            b4[1] = *(const float4*)(Bptr + (size_t)(k0 + 16) * N + 4);
        }

        #pragma unroll
        for (int k = 0; k < 16; k++) {
            float4 a0 = *(const float4*)(&As[k][ty * 4]);
            float4 a1 = *(const float4*)(&As[k][64 + ty * 4]);
            unsigned long long b2[4];
            const ulonglong2* bp0 = (const ulonglong2*)(&Bs[k][tx * 4]);
            ulonglong2 bl = bp0[0];
            b2[0] = bl.x; b2[1] = bl.y;
            const ulonglong2* bp1 = (const ulonglong2*)(&Bs[k][64 + tx * 4]);
            ulonglong2 bh = bp1[0];
            b2[2] = bh.x; b2[3] = bh.y;
            float av[8] = {a0.x, a0.y, a0.z, a0.w, a1.x, a1.y, a1.z, a1.w};
            #pragma unroll
            for (int i = 0; i < 8; i++) {
                const unsigned long long ad = f32x2_pack(av[i], av[i]);
                #pragma unroll
                for (int j = 0; j < 4; j++)
                    acc2[i][j] = f32x2_fma(ad, b2[j], acc2[i][j]);
            }
        }
        __syncthreads();
    }

    #pragma unroll
    for (int i = 0; i < 8; i++) {
        const int m = row0 + ((i < 4) ? (ty * 4 + i) : (64 + ty * 4 + i - 4));
        #pragma unroll
        for (int j = 0; j < 4; j++) {
            const int n = col0 + ((j < 2) ? (tx * 4 + j * 2) : (64 + tx * 4 + (j - 2) * 2));
            float lo, hi;
            f32x2_unpack(acc2[i][j], lo, hi);
            *(float2*)(&Cm[(size_t)m * N + n]) = make_float2(lo, hi);
        }
    }
}

// ---------------- fused rotation-GEMM + per-round argmax -> buckets ----------------
__global__ void __launch_bounds__(256, 2) rotbucket_kernel(
    const float* __restrict__ A, const float* __restrict__ Bm,
    int* __restrict__ buckets, int K)
{
    __shared__ float As[8][128];
    __shared__ float Bs[8][128];
    const int tid  = threadIdx.x;
    const int row0 = blockIdx.y * 128;
    const int tx = tid & 15;
    const int ty = tid >> 4;

    const int aRow = tid >> 1;
    const int aCol = (tid & 1) << 2;
    const int bRow = tid >> 5;
    const int bCol = (tid & 31) << 2;

    const float* Aptr = A + (size_t)(row0 + aRow) * K + aCol;
    const float* Bptr = Bm + (size_t)bRow * 128 + bCol;

    unsigned long long acc2[8][4];
    #pragma unroll
    for (int i = 0; i < 8; i++)
        #pragma unroll
        for (int j = 0; j < 4; j++) acc2[i][j] = 0ull;

    float4 a4 = *(const float4*)(Aptr);
    float4 b4 = *(const float4*)(Bptr);

    for (int k0 = 0; k0 < K; k0 += 8) {
        As[aCol + 0][aRow] = a4.x;
        As[aCol + 1][aRow] = a4.y;
        As[aCol + 2][aRow] = a4.z;
        As[aCol + 3][aRow] = a4.w;
        *(float4*)(&Bs[bRow][bCol]) = b4;
        __syncthreads();

        if (k0 + 8 < K) {
            a4 = *(const float4*)(Aptr + k0 + 8);
            b4 = *(const float4*)(Bptr + (size_t)(k0 + 8) * 128);
        }

        #pragma unroll
        for (int k = 0; k < 8; k++) {
            float4 a0 = *(const float4*)(&As[k][ty * 4]);
            float4 a1 = *(const float4*)(&As[k][64 + ty * 4]);
            unsigned long long b2[4];
            const unsigned long long* bp0 = (const unsigned long long*)(&Bs[k][tx * 4]);
            b2[0] = bp0[0];
            b2[1] = bp0[1];
            const unsigned long long* bp1 = (const unsigned long long*)(&Bs[k][64 + tx * 4]);
            b2[2] = bp1[0];
            b2[3] = bp1[1];
            float av[8] = {a0.x, a0.y, a0.z, a0.w, a1.x, a1.y, a1.z, a1.w};
            #pragma unroll
            for (int i = 0; i < 8; i++) {
                const unsigned long long ad = f32x2_pack(av[i], av[i]);
                #pragma unroll
                for (int j = 0; j < 4; j++)
                    acc2[i][j] = f32x2_fma(ad, b2[j], acc2[i][j]);
            }
        }
        __syncthreads();
    }

    const int txg = tx & 7;
    const int rA  = tx >> 3;
    #pragma unroll
    for (int i = 0; i < 8; i++) {
        const int m = row0 + ((i < 4) ? (ty * 4 + i) : (64 + ty * 4 + i - 4));
        #pragma unroll
        for (int half = 0; half < 2; half++) {
            float bv = -1e30f; int bi = 0;
            #pragma unroll
            for (int j = 0; j < 2; j++) {
                const int k = 4 * txg + j * 2;
                float lo, hi;
                f32x2_unpack(acc2[i][half * 2 + j], lo, hi);
                if (lo  > bv || (lo  == bv && k < bi))        { bv = lo;  bi = k; }
                if (hi  > bv || (hi  == bv && k + 1 < bi))    { bv = hi;  bi = k + 1; }
                if (-lo > bv || (-lo == bv && 32 + k < bi))   { bv = -lo; bi = 32 + k; }
                if (-hi > bv || (-hi == bv && 33 + k < bi))   { bv = -hi; bi = 33 + k; }
            }
            #pragma unroll
            for (int o = 1; o < 8; o <<= 1) {
                const float ov = __shfl_xor_sync(0xffffffffu, bv, o);
                const int   oi = __shfl_xor_sync(0xffffffffu, bi, o);
                if (ov > bv || (ov == bv && oi < bi)) { bv = ov; bi = oi; }
            }
            if (txg == 0) {
                const int r  = rA + half * 2;
                const int hh = m & (Hc - 1);
                const int ss = (m >> 4) & (Sc - 1);
                const int bb = m >> 16;
                buckets[(size_t)r * BHS + bb * (Hc * Sc) + hh * Sc + ss] = bi;
            }
        }
    }
}

// ---------------- fp16 tensor-core GEMM (m16n8k16), fp32 accum, k-tile 64 ----------------
#define TSH 72
#define HGEMM_SMEM (4*128*TSH*2)      // 73728 B

__global__ void __launch_bounds__(256, 2) hgemm_kernel(
    const __half* __restrict__ A, const __half* __restrict__ Bt,
    float* __restrict__ Cm, __half* __restrict__ Ch,
    const float* __restrict__ bias, const float* __restrict__ add,
    int M, int N, int K, int relu)
{
    extern __shared__ __half smh[];
    const uint32_t sb = smem_u32(smh);
    const uint32_t BUFSZ = 2 * 128 * TSH * 2;
    const uint32_t BOFFS = 128 * TSH * 2;

    const int tid  = threadIdx.x;
    const int lane = tid & 31;
    const int warp = tid >> 5;
    const int wm = warp >> 2;
    const int wn = warp & 3;
    const int row0 = blockIdx.y * 128;
    const int col0 = blockIdx.x * 128;

    const int r  = tid >> 1;
    const int hf = tid & 1;
    const __half* Ag = A  + (size_t)(row0 + r) * K + hf * 32;
    const __half* Bg = Bt + (size_t)(col0 + r) * K + hf * 32;
    const uint32_t adst0 = sb + (uint32_t)(r * TSH + hf * 32) * 2;
    const uint32_t bdst0 = adst0 + BOFFS;

    const int lm   = lane >> 3;
    const int lrow = (lm & 1) * 8 + (lane & 7);
    const int lkh  = lm >> 1;
    const uint32_t a_frag0 = sb + (uint32_t)((wm * 64 + lrow) * TSH) * 2 + lkh * 16;
    const int brow2 = ((lane >> 4) & 1) * 8 + (lane & 7);
    const int bkh   = (lane >> 3) & 1;
    const uint32_t b_frag0 = sb + BOFFS + (uint32_t)((wn * 32 + brow2) * TSH) * 2 + bkh * 16;

    float acc[4][4][4];
    #pragma unroll
    for (int mi = 0; mi < 4; mi++)
        #pragma unroll
        for (int ni = 0; ni < 4; ni++)
            #pragma unroll
            for (int c = 0; c < 4; c++) acc[mi][ni][c] = 0.f;

    const int T = K >> 6;

    #pragma unroll
    for (int i = 0; i < 4; i++) cp_async16cg(adst0 + i * 16, Ag + i * 8);
    #pragma unroll
    for (int i = 0; i < 4; i++) cp_async16cg(bdst0 + i * 16, Bg + i * 8);
    cp_commit();

    for (int t = 0; t < T; t++) {
        const int buf = t & 1;
        if (t + 1 < T) {
            const uint32_t ad = adst0 + (buf ^ 1) * BUFSZ;
            const uint32_t bd = bdst0 + (buf ^ 1) * BUFSZ;
            const __half* asrc = Ag + (t + 1) * 64;
            const __half* bsrc = Bg + (t + 1) * 64;
            #pragma unroll
            for (int i = 0; i < 4; i++) cp_async16cg(ad + i * 16, asrc + i * 8);
            #pragma unroll
            for (int i = 0; i < 4; i++) cp_async16cg(bd + i * 16, bsrc + i * 8);
        }
        cp_commit();
        cp_wait1();
        __syncthreads();

        const uint32_t abase = a_frag0 + buf * BUFSZ;
        const uint32_t bbase = b_frag0 + buf * BUFSZ;

        #pragma unroll
        for (int ks = 0; ks < 4; ks++) {
            uint32_t af[4][4];
            #pragma unroll
            for (int mi = 0; mi < 4; mi++)
                ldsm_x4(af[mi][0], af[mi][1], af[mi][2], af[mi][3],
                        abase + mi * (16 * TSH * 2) + ks * 32);
            uint32_t bf[4][2];
            #pragma unroll
            for (int p = 0; p < 2; p++)
                ldsm_x4(bf[2 * p][0], bf[2 * p][1], bf[2 * p + 1][0], bf[2 * p + 1][1],
                        bbase + p * (16 * TSH * 2) + ks * 32);
            #pragma unroll
            for (int mi = 0; mi < 4; mi++)
                #pragma unroll
                for (int ni = 0; ni < 4; ni++)
                    mma_f16(acc[mi][ni], af[mi][0], af[mi][1], af[mi][2], af[mi][3],
                            bf[ni][0], bf[ni][1]);
        }
        __syncthreads();
    }

    #pragma unroll
    for (int mi = 0; mi < 4; mi++) {
        #pragma unroll
        for (int ni = 0; ni < 4; ni++) {
            const int m = row0 + wm * 64 + mi * 16 + (lane >> 2);
            const int n = col0 + wn * 32 + ni * 8 + (lane & 3) * 2;
            float c0 = acc[mi][ni][0], c1 = acc[mi][ni][1];
            float c2 = acc[mi][ni][2], c3 = acc[mi][ni][3];
            if (bias) {
                const float b0 = __ldg(&bias[n]), b1 = __ldg(&bias[n + 1]);
                c0 += b0; c1 += b1; c2 += b0; c3 += b1;
            }
            if (add) {
                c0 += __ldg(&add[(size_t)m * N + n]);
                c1 += __ldg(&add[(size_t)m * N + n + 1]);
                c2 += __ldg(&add[(size_t)(m + 8) * N + n]);
                c3 += __ldg(&add[(size_t)(m + 8) * N + n + 1]);
            }
            if (relu) {
                c0 = fmaxf(c0, 0.f); c1 = fmaxf(c1, 0.f);
                c2 = fmaxf(c2, 0.f); c3 = fmaxf(c3, 0.f);
            }
            if (Ch) {
                *(__half2*)(&Ch[(size_t)m * N + n]) = __floats2half2_rn(c0, c1);
                *(__half2*)(&Ch[(size_t)(m + 8) * N + n]) = __floats2half2_rn(c2, c3);
            } else {
                *(float2*)(&Cm[(size_t)m * N + n]) = make_float2(c0, c1);
                *(float2*)(&Cm[(size_t)(m + 8) * N + n]) = make_float2(c2, c3);
            }
        }
    }
}

// ---------------- stable counting sort per (r,b,h); one round per launch ----------------
__global__ void sort_kernel(const int* __restrict__ buckets, int* __restrict__ order,
                            int grp_base)
{
    __shared__ int sb[Sc];
    __shared__ int cnt[NBc];
    __shared__ int off[NBc];
    const size_t base = (size_t)(grp_base + blockIdx.x) * Sc;
    const int tid = threadIdx.x;
    if (tid < NBc) cnt[tid] = 0;
    __syncthreads();
    for (int i = tid; i < Sc; i += blockDim.x) {
        int bk = buckets[base + i];
        sb[i] = bk;
        atomicAdd(&cnt[bk], 1);
    }
    __syncthreads();
    if (tid == 0) {
        int a = 0;
        for (int k = 0; k < NBc; k++) { off[k] = a; a += cnt[k]; }
    }
    __syncthreads();
    if (tid < NBc) {
        int o = off[tid];
        for (int i = 0; i < Sc; i++)
            if (sb[i] == tid) order[base + (o++)] = i;
    }
}

// ---------------- chunked LSH attention: 2 chunks per CTA, one round per launch ----------------
#define ATTN_SMEM (2*192*DHc*4 + 2*192*4)   // 99840 B

__global__ void __launch_bounds__(128) attn_kernel(
    const float* __restrict__ qk, const float* __restrict__ v,
    const int* __restrict__ order, const int* __restrict__ buckets,
    float* __restrict__ oall, float* __restrict__ lall, int r)
{
    extern __shared__ float smemf[];
    float* Ke = smemf;
    float* Ve = smemf + 192 * DHc;
    int*   be = (int*)(smemf + 2 * 192 * DHc);
    int*   pe = be + 192;

    const int blk = blockIdx.x;
    const int np = blk & 31;
    const int h  = (blk >> 5) & (Hc - 1);
    const int b  = blk >> 9;
    const size_t rbh = (((size_t)r * Bc + b) * Hc + h) * Sc;
    const int tid = threadIdx.x;

    for (int j = tid; j < 192; j += 128) {
        const int ci = j >> 6;
        const int chunk = (2 * np + ci + NCHc - 1) & (NCHc - 1);
        const int spos = chunk * Cc + (j & 63);
        const int pk = order[rbh + spos];
        const float* kr = qk + ((size_t)(b * Sc + pk)) * Dc + h * DHc;
        const float* vr = v  + ((size_t)(b * Sc + pk)) * Dc + h * DHc;
        float ss = 0.f;
        float tmp[DHc];
        #pragma unroll
        for (int d = 0; d < DHc; d++) { float x = kr[d]; tmp[d] = x; ss = fmaf(x, x, ss); }
        const float sc = 1.f / (sqrtf(ss) + 1e-6f);
        #pragma unroll
        for (int d = 0; d < DHc; d++) { Ke[j * DHc + d] = tmp[d] * sc; Ve[j * DHc + d] = vr[d]; }
        be[j] = buckets[rbh + pk];
        pe[j] = pk;
    }
    __syncthreads();

    const int qc = tid >> 6;
    const int qi = tid & 63;
    const int curb  = 64 + qc * 64;
    const int prevb = qc * 64;
    const int self  = curb + qi;
    const int p  = pe[self];
    const int bq = be[self];

    unsigned long long q2[32];
    {
        const float* qr = qk + ((size_t)(b * Sc + p)) * Dc + h * DHc;
        const unsigned long long* q8 = (const unsigned long long*)qr;
        #pragma unroll
        for (int i = 0; i < 32; i++) q2[i] = q8[i];
    }

    unsigned long long acc2[32];
    #pragma unroll
    for (int i = 0; i < 32; i++) acc2[i] = 0ull;
    float sum = 0.f;

    #pragma unroll 1
    for (int seg = 0; seg < 2; seg++) {
        const int base = seg ? prevb : curb;
        #pragma unroll 1
        for (int jj = 0; jj < Cc; jj++) {
            const int j = base + jj;
            const ulonglong2* k4 = (const ulonglong2*)(Ke + j * DHc);
            unsigned long long sA = 0, sB = 0, sC = 0, sD = 0;
            #pragma unroll
            for (int i = 0; i < 8; i++) {
                ulonglong2 k0 = k4[2 * i];
                ulonglong2 k1 = k4[2 * i + 1];
                sA = f32x2_fma(q2[4 * i + 0], k0.x, sA);
                sB = f32x2_fma(q2[4 * i + 1], k0.y, sB);
                sC = f32x2_fma(q2[4 * i + 2], k1.x, sC);
                sD = f32x2_fma(q2[4 * i + 3], k1.y, sD);
            }
            float a0, a1, b0, b1, c0, c1, d0, d1;
            f32x2_unpack(sA, a0, a1); f32x2_unpack(sB, b0, b1);
            f32x2_unpack(sC, c0, c1); f32x2_unpack(sD, d0, d1);
            float s = (((a0 + a1) + (b0 + b1)) + ((c0 + c1) + (d0 + d1))) * 0.125f;
            if (bq != be[j]) s = -1e9f;
            if (p == pe[j])  s = -1e5f;
            const float e = __expf(s);
            sum += e;
            const unsigned long long e2 = f32x2_pack(e, e);
            const ulonglong2* v4 = (const ulonglong2*)(Ve + j * DHc);
            #pragma unroll
            for (int i = 0; i < 16; i++) {
                ulonglong2 vv = v4[i];
                acc2[2 * i + 0] = f32x2_fma(e2, vv.x, acc2[2 * i + 0]);
                acc2[2 * i + 1] = f32x2_fma(e2, vv.y, acc2[2 * i + 1]);
            }
        }
    }

    float* orow = oall + (rbh + p) * DHc;
    if (sum > 0.f) {
        const float linv = 1.f / sum;
        const unsigned long long l2 = f32x2_pack(linv, linv);
        unsigned long long* o8 = (unsigned long long*)orow;
        #pragma unroll
        for (int i = 0; i < 32; i++) o8[i] = f32x2_mul(acc2[i], l2);
        lall[rbh + p] = logf(sum);
    } else {
        const float* vs = Ve + self * DHc;
        #pragma unroll
        for (int d = 0; d < DHc; d++) orow[d] = vs[d];
        lall[rbh + p] = -1e5f;
    }
}

// ---------------- combine rounds -> fp16 output ----------------
__global__ void combine_kernel(const float* __restrict__ oall, const float* __restrict__ lall,
                               __half* __restrict__ out)
{
    const int t = blockIdx.x * blockDim.x + threadIdx.x;
    if (t >= BHS) return;
    const int s = t & (Sc - 1);
    const int h = (t >> 12) & (Hc - 1);
    const int b = t >> 16;
    const size_t idx = (size_t)t;
    const float l0 = lall[idx], l1 = lall[idx + BHS], l2 = lall[idx + 2 * (size_t)BHS], l3 = lall[idx + 3 * (size_t)BHS];
    const float m = fmaxf(fmaxf(l0, l1), fmaxf(l2, l3));
    float w0 = expf(l0 - m), w1 = expf(l1 - m), w2 = expf(l2 - m), w3 = expf(l3 - m);
    const float inv = 1.f / (w0 + w1 + w2 + w3);
    w0 *= inv; w1 *= inv; w2 *= inv; w3 *= inv;
    const float* o0 = oall + idx * DHc;
    const float* o1 = oall + (idx + BHS) * DHc;
    const float* o2 = oall + (idx + 2 * (size_t)BHS) * DHc;
    const float* o3 = oall + (idx + 3 * (size_t)BHS) * DHc;
    __half* dst = out + ((size_t)(b * Sc + s)) * Dc + h * DHc;
    #pragma unroll
    for (int d = 0; d < DHc; d++)
        dst[d] = __float2half_rn(w0 * o0[d] + w1 * o1[d] + w2 * o2[d] + w3 * o3[d]);
}

// ---------------- launch ----------------
extern "C" void kernel_launch(void* const* d_in, const int* in_sizes, int n_in,
                              void* d_out, int out_size)
{
    const float* x1    = (const float*)d_in[0];
    const float* x2    = (const float*)d_in[1];
    const float* Wqk   = (const float*)d_in[2];
    const float* Wv    = (const float*)d_in[3];
    const float* Wo    = (const float*)d_in[4];
    const float* ln1_g = (const float*)d_in[5];
    const float* ln1_b = (const float*)d_in[6];
    const float* W1    = (const float*)d_in[7];
    const float* bf1   = (const float*)d_in[8];
    const float* W2    = (const float*)d_in[9];
    const float* bf2   = (const float*)d_in[10];
    const float* ln2_g = (const float*)d_in[11];
    const float* ln2_b = (const float*)d_in[12];
    const float* rot   = (const float*)d_in[13];

    float *ln, *qk, *vv, *oall, *lall;
    __half *lnh, *attnh, *ffhh, *WvT, *WoT, *W1T, *W2T;
    int *bk, *ord;
    cudaGetSymbolAddress((void**)&ln,    g_ln);
    cudaGetSymbolAddress((void**)&lnh,   g_lnh);
    cudaGetSymbolAddress((void**)&qk,    g_qk);
    cudaGetSymbolAddress((void**)&vv,    g_v);
    cudaGetSymbolAddress((void**)&attnh, g_attnh);
    cudaGetSymbolAddress((void**)&ffhh,  g_ffhh);
    cudaGetSymbolAddress((void**)&oall,  g_oall);
    cudaGetSymbolAddress((void**)&lall,  g_lall);
    cudaGetSymbolAddress((void**)&bk,    g_buckets);
    cudaGetSymbolAddress((void**)&ord,   g_order);
    cudaGetSymbolAddress((void**)&WvT,   g_WvT);
    cudaGetSymbolAddress((void**)&WoT,   g_WoT);
    cudaGetSymbolAddress((void**)&W1T,   g_W1T);
    cudaGetSymbolAddress((void**)&W2T,   g_W2T);

    static cudaStream_t s2 = nullptr;
    static cudaEvent_t evT = nullptr, evF = nullptr, evJ = nullptr;
    static cudaEvent_t evS[Rc] = {nullptr, nullptr, nullptr, nullptr};
    static cudaEvent_t evA = nullptr;
    if (!s2) {
        cudaStreamCreateWithFlags(&s2, cudaStreamNonBlocking);
        cudaEventCreateWithFlags(&evT, cudaEventDisableTiming);
        cudaEventCreateWithFlags(&evF, cudaEventDisableTiming);
        cudaEventCreateWithFlags(&evJ, cudaEventDisableTiming);
        cudaEventCreateWithFlags(&evA, cudaEventDisableTiming);
        for (int r = 0; r < Rc; r++) cudaEventCreateWithFlags(&evS[r], cudaEventDisableTiming);
    }

    float* y1 = (float*)d_out;
    float* y2 = y1 + BSD;

    const int ROWS = Bc * Sc;   // 8192

    cudaFuncSetAttribute(hgemm_kernel, cudaFuncAttributeMaxDynamicSharedMemorySize, HGEMM_SMEM);
    cudaFuncSetAttribute(attn_kernel, cudaFuncAttributeMaxDynamicSharedMemorySize, ATTN_SMEM);

    // fork early: all weight transposes on s2
    cudaEventRecord(evT, 0);
    cudaStreamWaitEvent(s2, evT, 0);
    transpose_half_kernel<<<dim3(Dc / 32,  Dc / 32),  256, 0, s2>>>(Wv, WvT, Dc,  Dc);
    transpose_half_kernel<<<dim3(Dc / 32,  Dc / 32),  256, 0, s2>>>(Wo, WoT, Dc,  Dc);
    transpose_half_kernel<<<dim3(DFFc / 32, Dc / 32), 256, 0, s2>>>(W1, W1T, Dc,  DFFc);
    transpose_half_kernel<<<dim3(Dc / 32, DFFc / 32), 256, 0, s2>>>(W2, W2T, DFFc, Dc);

    // ln1 on stream 0 (fp32 copy for exact qk; fp16 copy for v)
    ln_kernel<<<ROWS, 256>>>(x2, ln1_g, ln1_b, ln, lnh);
    cudaEventRecord(evF, 0);
    cudaStreamWaitEvent(s2, evF, 0);

    // v fp16 GEMM on s2; qk chain on stream 0
    dim3 gD(Dc / 128, ROWS / 128);
    hgemm_kernel<<<gD, 256, HGEMM_SMEM, s2>>>(lnh, WvT, vv, nullptr, nullptr, nullptr, ROWS, Dc, Dc, 0);

    sgemm_kernel<<<gD, 256>>>(ln, Wqk, qk, ROWS, Dc, Dc);
    rotbucket_kernel<<<dim3(1, BHS / 128), 256>>>(qk, rot, bk, DHc);

    cudaEventRecord(evJ, s2);
    cudaStreamWaitEvent(0, evJ, 0);   // attn also needs v; join before attn launches

    // per-round sort (stream 0) -> attn (s2) pipeline
    for (int r = 0; r < Rc; r++) {
        sort_kernel<<<Bc * Hc, 256>>>(bk, ord, r * Bc * Hc);
        cudaEventRecord(evS[r], 0);
        cudaStreamWaitEvent(s2, evS[r], 0);
        attn_kernel<<<Bc * Hc * (NCHc / 2), 128, ATTN_SMEM, s2>>>(qk, vv, ord, bk, oall, lall, r);
    }
    cudaEventRecord(evA, s2);
    cudaStreamWaitEvent(0, evA, 0);

    combine_kernel<<<BHS / 256, 256>>>(oall, lall, attnh);

    hgemm_kernel<<<gD, 256, HGEMM_SMEM>>>(attnh, WoT, y1, nullptr, nullptr, x1, ROWS, Dc, Dc, 0);

    ln_kernel<<<ROWS, 256>>>(y1, ln2_g, ln2_b, nullptr, lnh);

    dim3 gF(DFFc / 128, ROWS / 128);
    hgemm_kernel<<<gF, 256, HGEMM_SMEM>>>(lnh, W1T, nullptr, ffhh, bf1, nullptr, ROWS, DFFc, Dc, 1);
    hgemm_kernel<<<gD, 256, HGEMM_SMEM>>>(ffhh, W2T, y2, nullptr, bf2, x2, ROWS, Dc, DFFc, 0);
}

// round 16
// speedup vs baseline: 1.1401x; 1.1401x over previous
#include <cuda_runtime.h>
#include <cuda_fp16.h>
#include <math.h>
#include <stdint.h>

// ---------------- problem dims ----------------
#define Bc   2
#define Sc   4096
#define Dc   1024
#define Hc   16
#define NBc  64
#define NB2c 32
#define Rc   4
#define DFFc 4096
#define DHc  64
#define Cc   64
#define NCHc 64
#define BHS  (Bc*Hc*Sc)          // 131072
#define BSD  ((size_t)Bc*Sc*Dc)  // 8388608

// ---------------- workspace (static device memory; no allocations) ----------------
__device__ float  g_ln[BSD];
__device__ __half g_lnh[BSD];
__device__ float  g_qk[BSD];
__device__ float  g_v[BSD];
__device__ __half g_attnh[BSD];
__device__ __half g_ffhh[(size_t)Bc*Sc*DFFc];
__device__ float  g_oall[(size_t)Rc*BHS*DHc];
__device__ float  g_lall[(size_t)Rc*BHS];
__device__ int    g_buckets[(size_t)Rc*BHS];
__device__ int    g_order[(size_t)Rc*BHS];
__device__ __half g_WvT[(size_t)Dc*Dc];
__device__ __half g_WoT[(size_t)Dc*Dc];
__device__ __half g_W1T[(size_t)DFFc*Dc];
__device__ __half g_W2T[(size_t)Dc*DFFc];

// ---------------- packed f32x2 helpers ----------------
__device__ __forceinline__ unsigned long long f32x2_pack(float lo, float hi) {
    unsigned long long r;
    asm("mov.b64 %0, {%1, %2};" : "=l"(r) : "f"(lo), "f"(hi));
    return r;
}
__device__ __forceinline__ unsigned long long f32x2_fma(unsigned long long a,
                                                        unsigned long long b,
                                                        unsigned long long c) {
    unsigned long long d;
    asm("fma.rn.f32x2 %0, %1, %2, %3;" : "=l"(d) : "l"(a), "l"(b), "l"(c));
    return d;
}
__device__ __forceinline__ unsigned long long f32x2_mul(unsigned long long a,
                                                        unsigned long long b) {
    unsigned long long d;
    asm("mul.rn.f32x2 %0, %1, %2;" : "=l"(d) : "l"(a), "l"(b));
    return d;
}
__device__ __forceinline__ void f32x2_unpack(unsigned long long v, float& lo, float& hi) {
    asm("mov.b64 {%0, %1}, %2;" : "=f"(lo), "=f"(hi) : "l"(v));
}

// ---------------- mma / cp.async / ldmatrix helpers ----------------
__device__ __forceinline__ void mma_f16(float c[4],
                                        uint32_t a0, uint32_t a1, uint32_t a2, uint32_t a3,
                                        uint32_t b0, uint32_t b1) {
    asm volatile(
        "mma.sync.aligned.m16n8k16.row.col.f32.f16.f16.f32 "
        "{%0,%1,%2,%3}, {%4,%5,%6,%7}, {%8,%9}, {%0,%1,%2,%3};"
        : "+f"(c[0]), "+f"(c[1]), "+f"(c[2]), "+f"(c[3])
        : "r"(a0), "r"(a1), "r"(a2), "r"(a3), "r"(b0), "r"(b1));
}
__device__ __forceinline__ uint32_t smem_u32(const void* p) {
    uint32_t a;
    asm("{ .reg .u64 t; cvta.to.shared.u64 t, %1; cvt.u32.u64 %0, t; }" : "=r"(a) : "l"(p));
    return a;
}
__device__ __forceinline__ void cp_async16(uint32_t dst, const void* src) {
    asm volatile("cp.async.ca.shared.global [%0], [%1], 16;" :: "r"(dst), "l"(src));
}
__device__ __forceinline__ void cp_commit() {
    asm volatile("cp.async.commit_group;" ::: "memory");
}
__device__ __forceinline__ void cp_wait1() {
    asm volatile("cp.async.wait_group 1;" ::: "memory");
}
__device__ __forceinline__ void ldsm_x4(uint32_t& r0, uint32_t& r1, uint32_t& r2, uint32_t& r3,
                                        uint32_t addr) {
    asm volatile("ldmatrix.sync.aligned.m8n8.x4.shared.b16 {%0,%1,%2,%3}, [%4];"
                 : "=r"(r0), "=r"(r1), "=r"(r2), "=r"(r3) : "r"(addr));
}

// ---------------- weight transpose to fp16 ----------------
__global__ void transpose_half_kernel(const float* __restrict__ W, __half* __restrict__ Wt,
                                      int K, int N)
{
    __shared__ float tile[32][33];
    const int bn = blockIdx.x * 32;
    const int bk = blockIdx.y * 32;
    const int tx = threadIdx.x & 31;
    const int ty = threadIdx.x >> 5;
    #pragma unroll
    for (int i = 0; i < 32; i += 8)
        tile[ty + i][tx] = W[(size_t)(bk + ty + i) * N + bn + tx];
    __syncthreads();
    #pragma unroll
    for (int i = 0; i < 32; i += 8)
        Wt[(size_t)(bn + ty + i) * K + bk + tx] = __float2half_rn(tile[tx][ty + i]);
}

// ---------------- layernorm (vectorized float4): fp32 (optional) + fp16 (optional) ----------------
__global__ void ln_kernel(const float* __restrict__ x, const float* __restrict__ g,
                          const float* __restrict__ bb, float* __restrict__ y,
                          __half* __restrict__ yh)
{
    const int row = blockIdx.x;
    const int tid = threadIdx.x;
    const float4 v = ((const float4*)(x + (size_t)row * Dc))[tid];
    float s1 = ((v.x + v.y) + (v.z + v.w));
    float s2 = fmaf(v.x, v.x, fmaf(v.y, v.y, fmaf(v.z, v.z, v.w * v.w)));

    __shared__ float sh1[8], sh2[8];
    const int lane = tid & 31, w = tid >> 5;
    #pragma unroll
    for (int o = 16; o > 0; o >>= 1) {
        s1 += __shfl_xor_sync(~0u, s1, o);
        s2 += __shfl_xor_sync(~0u, s2, o);
    }
    if (lane == 0) { sh1[w] = s1; sh2[w] = s2; }
    __syncthreads();
    if (w == 0) {
        s1 = (lane < 8) ? sh1[lane] : 0.f;
        s2 = (lane < 8) ? sh2[lane] : 0.f;
        #pragma unroll
        for (int o = 4; o > 0; o >>= 1) {
            s1 += __shfl_xor_sync(~0u, s1, o);
            s2 += __shfl_xor_sync(~0u, s2, o);
        }
        if (lane == 0) { sh1[0] = s1; sh2[0] = s2; }
    }
    __syncthreads();
    const float mean = sh1[0] * (1.f / Dc);
    const float var  = sh2[0] * (1.f / Dc) - mean * mean;
    const float inv  = 1.f / sqrtf(var + 1e-5f);

    const float4 gg = ((const float4*)g)[tid];
    const float4 b4 = ((const float4*)bb)[tid];
    float4 o;
    o.x = (v.x - mean) * inv * gg.x + b4.x;
    o.y = (v.y - mean) * inv * gg.y + b4.y;
    o.z = (v.z - mean) * inv * gg.z + b4.z;
    o.w = (v.w - mean) * inv * gg.w + b4.w;
    if (y) ((float4*)(y + (size_t)row * Dc))[tid] = o;
    if (yh) {
        __half2 h0 = __floats2half2_rn(o.x, o.y);
        __half2 h1 = __floats2half2_rn(o.z, o.w);
        uint32_t u0, u1;
        u0 = *(uint32_t*)&h0; u1 = *(uint32_t*)&h1;
        ((uint2*)(yh + (size_t)row * Dc))[tid] = make_uint2(u0, u1);
    }
}

// ---------------- exact fp32 SGEMM (FFMA2), k-tile 16: qk projection ----------------
__global__ void __launch_bounds__(256, 2) sgemm_kernel(
    const float* __restrict__ A, const float* __restrict__ Bm,
    float* __restrict__ Cm, int M, int N, int K)
{
    __shared__ float As[16][128];
    __shared__ float Bs[16][128];
    const int tid  = threadIdx.x;
    const int row0 = blockIdx.y * 128;
    const int col0 = blockIdx.x * 128;
    const int tx = tid & 15;
    const int ty = tid >> 4;

    const int aRow = tid >> 1;
    const int aCol = (tid & 1) << 3;
    const int bRow = tid >> 4;
    const int bCol = (tid & 15) << 3;

    const float* Aptr = A + (size_t)(row0 + aRow) * K + aCol;
    const float* Bptr = Bm + (size_t)bRow * N + col0 + bCol;

    unsigned long long acc2[8][4];
    #pragma unroll
    for (int i = 0; i < 8; i++)
        #pragma unroll
        for (int j = 0; j < 4; j++) acc2[i][j] = 0ull;

    float4 a4[2], b4[2];
    a4[0] = *(const float4*)(Aptr);
    a4[1] = *(const float4*)(Aptr + 4);
    b4[0] = *(const float4*)(Bptr);
    b4[1] = *(const float4*)(Bptr + 4);

    for (int k0 = 0; k0 < K; k0 += 16) {
        #pragma unroll
        for (int q = 0; q < 2; q++) {
            As[aCol + q * 4 + 0][aRow] = a4[q].x;
            As[aCol + q * 4 + 1][aRow] = a4[q].y;
            As[aCol + q * 4 + 2][aRow] = a4[q].z;
            As[aCol + q * 4 + 3][aRow] = a4[q].w;
        }
        *(float4*)(&Bs[bRow][bCol])     = b4[0];
        *(float4*)(&Bs[bRow][bCol + 4]) = b4[1];
        __syncthreads();

        if (k0 + 16 < K) {
            a4[0] = *(const float4*)(Aptr + k0 + 16);
            a4[1] = *(const float4*)(Aptr + k0 + 20);
            b4[0] = *(const float4*)(Bptr + (size_t)(k0 + 16) * N);
            b4[1] = *(const float4*)(Bptr + (size_t)(k0 + 16) * N + 4);
        }

        #pragma unroll
        for (int k = 0; k < 16; k++) {
            float4 a0 = *(const float4*)(&As[k][ty * 4]);
            float4 a1 = *(const float4*)(&As[k][64 + ty * 4]);
            unsigned long long b2[4];
            const ulonglong2* bp0 = (const ulonglong2*)(&Bs[k][tx * 4]);
            ulonglong2 bl = bp0[0];
            b2[0] = bl.x; b2[1] = bl.y;
            const ulonglong2* bp1 = (const ulonglong2*)(&Bs[k][64 + tx * 4]);
            ulonglong2 bh = bp1[0];
            b2[2] = bh.x; b2[3] = bh.y;
            float av[8] = {a0.x, a0.y, a0.z, a0.w, a1.x, a1.y, a1.z, a1.w};
            #pragma unroll
            for (int i = 0; i < 8; i++) {
                const unsigned long long ad = f32x2_pack(av[i], av[i]);
                #pragma unroll
                for (int j = 0; j < 4; j++)
                    acc2[i][j] = f32x2_fma(ad, b2[j], acc2[i][j]);
            }
        }
        __syncthreads();
    }

    #pragma unroll
    for (int i = 0; i < 8; i++) {
        const int m = row0 + ((i < 4) ? (ty * 4 + i) : (64 + ty * 4 + i - 4));
        #pragma unroll
        for (int j = 0; j < 4; j++) {
            const int n = col0 + ((j < 2) ? (tx * 4 + j * 2) : (64 + tx * 4 + (j - 2) * 2));
            float lo, hi;
            f32x2_unpack(acc2[i][j], lo, hi);
            *(float2*)(&Cm[(size_t)m * N + n]) = make_float2(lo, hi);
        }
    }
}

// ---------------- fused rotation-GEMM + per-round argmax -> buckets ----------------
__global__ void __launch_bounds__(256, 2) rotbucket_kernel(
    const float* __restrict__ A, const float* __restrict__ Bm,
    int* __restrict__ buckets, int K)
{
    __shared__ float As[8][128];
    __shared__ float Bs[8][128];
    const int tid  = threadIdx.x;
    const int row0 = blockIdx.y * 128;
    const int tx = tid & 15;
    const int ty = tid >> 4;

    const int aRow = tid >> 1;
    const int aCol = (tid & 1) << 2;
    const int bRow = tid >> 5;
    const int bCol = (tid & 31) << 2;

    const float* Aptr = A + (size_t)(row0 + aRow) * K + aCol;
    const float* Bptr = Bm + (size_t)bRow * 128 + bCol;

    unsigned long long acc2[8][4];
    #pragma unroll
    for (int i = 0; i < 8; i++)
        #pragma unroll
        for (int j = 0; j < 4; j++) acc2[i][j] = 0ull;

    float4 a4 = *(const float4*)(Aptr);
    float4 b4 = *(const float4*)(Bptr);

    for (int k0 = 0; k0 < K; k0 += 8) {
        As[aCol + 0][aRow] = a4.x;
        As[aCol + 1][aRow] = a4.y;
        As[aCol + 2][aRow] = a4.z;
        As[aCol + 3][aRow] = a4.w;
        *(float4*)(&Bs[bRow][bCol]) = b4;
        __syncthreads();

        if (k0 + 8 < K) {
            a4 = *(const float4*)(Aptr + k0 + 8);
            b4 = *(const float4*)(Bptr + (size_t)(k0 + 8) * 128);
        }

        #pragma unroll
        for (int k = 0; k < 8; k++) {
            float4 a0 = *(const float4*)(&As[k][ty * 4]);
            float4 a1 = *(const float4*)(&As[k][64 + ty * 4]);
            unsigned long long b2[4];
            const unsigned long long* bp0 = (const unsigned long long*)(&Bs[k][tx * 4]);
            b2[0] = bp0[0];
            b2[1] = bp0[1];
            const unsigned long long* bp1 = (const unsigned long long*)(&Bs[k][64 + tx * 4]);
            b2[2] = bp1[0];
            b2[3] = bp1[1];
            float av[8] = {a0.x, a0.y, a0.z, a0.w, a1.x, a1.y, a1.z, a1.w};
            #pragma unroll
            for (int i = 0; i < 8; i++) {
                const unsigned long long ad = f32x2_pack(av[i], av[i]);
                #pragma unroll
                for (int j = 0; j < 4; j++)
                    acc2[i][j] = f32x2_fma(ad, b2[j], acc2[i][j]);
            }
        }
        __syncthreads();
    }

    const int txg = tx & 7;
    const int rA  = tx >> 3;
    #pragma unroll
    for (int i = 0; i < 8; i++) {
        const int m = row0 + ((i < 4) ? (ty * 4 + i) : (64 + ty * 4 + i - 4));
        #pragma unroll
        for (int half = 0; half < 2; half++) {
            float bv = -1e30f; int bi = 0;
            #pragma unroll
            for (int j = 0; j < 2; j++) {
                const int k = 4 * txg + j * 2;
                float lo, hi;
                f32x2_unpack(acc2[i][half * 2 + j], lo, hi);
                if (lo  > bv || (lo  == bv && k < bi))        { bv = lo;  bi = k; }
                if (hi  > bv || (hi  == bv && k + 1 < bi))    { bv = hi;  bi = k + 1; }
                if (-lo > bv || (-lo == bv && 32 + k < bi))   { bv = -lo; bi = 32 + k; }
                if (-hi > bv || (-hi == bv && 33 + k < bi))   { bv = -hi; bi = 33 + k; }
            }
            #pragma unroll
            for (int o = 1; o < 8; o <<= 1) {
                const float ov = __shfl_xor_sync(0xffffffffu, bv, o);
                const int   oi = __shfl_xor_sync(0xffffffffu, bi, o);
                if (ov > bv || (ov == bv && oi < bi)) { bv = ov; bi = oi; }
            }
            if (txg == 0) {
                const int r  = rA + half * 2;
                const int hh = m & (Hc - 1);
                const int ss = (m >> 4) & (Sc - 1);
                const int bb = m >> 16;
                buckets[(size_t)r * BHS + bb * (Hc * Sc) + hh * Sc + ss] = bi;
            }
        }
    }
}

// ---------------- fp16 tensor-core GEMM (m16n8k16), fp32 accum, k-tile 64 ----------------
#define TSH 72
#define HGEMM_SMEM (4*128*TSH*2)      // 73728 B

__global__ void __launch_bounds__(256, 2) hgemm_kernel(
    const __half* __restrict__ A, const __half* __restrict__ Bt,
    float* __restrict__ Cm, __half* __restrict__ Ch,
    const float* __restrict__ bias, const float* __restrict__ add,
    int M, int N, int K, int relu)
{
    extern __shared__ __half smh[];
    const uint32_t sb = smem_u32(smh);
    const uint32_t BUFSZ = 2 * 128 * TSH * 2;
    const uint32_t BOFFS = 128 * TSH * 2;

    const int tid  = threadIdx.x;
    const int lane = tid & 31;
    const int warp = tid >> 5;
    const int wm = warp >> 2;
    const int wn = warp & 3;
    const int row0 = blockIdx.y * 128;
    const int col0 = blockIdx.x * 128;

    const int r  = tid >> 1;
    const int hf = tid & 1;
    const __half* Ag = A  + (size_t)(row0 + r) * K + hf * 32;
    const __half* Bg = Bt + (size_t)(col0 + r) * K + hf * 32;
    const uint32_t adst0 = sb + (uint32_t)(r * TSH + hf * 32) * 2;
    const uint32_t bdst0 = adst0 + BOFFS;

    const int lm   = lane >> 3;
    const int lrow = (lm & 1) * 8 + (lane & 7);
    const int lkh  = lm >> 1;
    const uint32_t a_frag0 = sb + (uint32_t)((wm * 64 + lrow) * TSH) * 2 + lkh * 16;
    const int brow2 = ((lane >> 4) & 1) * 8 + (lane & 7);
    const int bkh   = (lane >> 3) & 1;
    const uint32_t b_frag0 = sb + BOFFS + (uint32_t)((wn * 32 + brow2) * TSH) * 2 + bkh * 16;

    float acc[4][4][4];
    #pragma unroll
    for (int mi = 0; mi < 4; mi++)
        #pragma unroll
        for (int ni = 0; ni < 4; ni++)
            #pragma unroll
            for (int c = 0; c < 4; c++) acc[mi][ni][c] = 0.f;

    const int T = K >> 6;

    #pragma unroll
    for (int i = 0; i < 4; i++) cp_async16(adst0 + i * 16, Ag + i * 8);
    #pragma unroll
    for (int i = 0; i < 4; i++) cp_async16(bdst0 + i * 16, Bg + i * 8);
    cp_commit();

    for (int t = 0; t < T; t++) {
        const int buf = t & 1;
        if (t + 1 < T) {
            const uint32_t ad = adst0 + (buf ^ 1) * BUFSZ;
            const uint32_t bd = bdst0 + (buf ^ 1) * BUFSZ;
            const __half* asrc = Ag + (t + 1) * 64;
            const __half* bsrc = Bg + (t + 1) * 64;
            #pragma unroll
            for (int i = 0; i < 4; i++) cp_async16(ad + i * 16, asrc + i * 8);
            #pragma unroll
            for (int i = 0; i < 4; i++) cp_async16(bd + i * 16, bsrc + i * 8);
        }
        cp_commit();
        cp_wait1();
        __syncthreads();

        const uint32_t abase = a_frag0 + buf * BUFSZ;
        const uint32_t bbase = b_frag0 + buf * BUFSZ;

        #pragma unroll
        for (int ks = 0; ks < 4; ks++) {
            uint32_t af[4][4];
            #pragma unroll
            for (int mi = 0; mi < 4; mi++)
                ldsm_x4(af[mi][0], af[mi][1], af[mi][2], af[mi][3],
                        abase + mi * (16 * TSH * 2) + ks * 32);
            uint32_t bf[4][2];
            #pragma unroll
            for (int p = 0; p < 2; p++)
                ldsm_x4(bf[2 * p][0], bf[2 * p][1], bf[2 * p + 1][0], bf[2 * p + 1][1],
                        bbase + p * (16 * TSH * 2) + ks * 32);
            #pragma unroll
            for (int mi = 0; mi < 4; mi++)
                #pragma unroll
                for (int ni = 0; ni < 4; ni++)
                    mma_f16(acc[mi][ni], af[mi][0], af[mi][1], af[mi][2], af[mi][3],
                            bf[ni][0], bf[ni][1]);
        }
        __syncthreads();
    }

    #pragma unroll
    for (int mi = 0; mi < 4; mi++) {
        #pragma unroll
        for (int ni = 0; ni < 4; ni++) {
            const int m = row0 + wm * 64 + mi * 16 + (lane >> 2);
            const int n = col0 + wn * 32 + ni * 8 + (lane & 3) * 2;
            float c0 = acc[mi][ni][0], c1 = acc[mi][ni][1];
            float c2 = acc[mi][ni][2], c3 = acc[mi][ni][3];
            if (bias) {
                const float b0 = __ldg(&bias[n]), b1 = __ldg(&bias[n + 1]);
                c0 += b0; c1 += b1; c2 += b0; c3 += b1;
            }
            if (add) {
                c0 += __ldg(&add[(size_t)m * N + n]);
                c1 += __ldg(&add[(size_t)m * N + n + 1]);
                c2 += __ldg(&add[(size_t)(m + 8) * N + n]);
                c3 += __ldg(&add[(size_t)(m + 8) * N + n + 1]);
            }
            if (relu) {
                c0 = fmaxf(c0, 0.f); c1 = fmaxf(c1, 0.f);
                c2 = fmaxf(c2, 0.f); c3 = fmaxf(c3, 0.f);
            }
            if (Ch) {
                *(__half2*)(&Ch[(size_t)m * N + n]) = __floats2half2_rn(c0, c1);
                *(__half2*)(&Ch[(size_t)(m + 8) * N + n]) = __floats2half2_rn(c2, c3);
            } else {
                *(float2*)(&Cm[(size_t)m * N + n]) = make_float2(c0, c1);
                *(float2*)(&Cm[(size_t)(m + 8) * N + n]) = make_float2(c2, c3);
            }
        }
    }
}

// ---------------- stable counting sort per (r,b,h) ----------------
__global__ void sort_kernel(const int* __restrict__ buckets, int* __restrict__ order)
{
    __shared__ int sb[Sc];
    __shared__ int cnt[NBc];
    __shared__ int off[NBc];
    const size_t base = (size_t)blockIdx.x * Sc;
    const int tid = threadIdx.x;
    if (tid < NBc) cnt[tid] = 0;
    __syncthreads();
    for (int i = tid; i < Sc; i += blockDim.x) {
        int bk = buckets[base + i];
        sb[i] = bk;
        atomicAdd(&cnt[bk], 1);
    }
    __syncthreads();
    if (tid == 0) {
        int a = 0;
        for (int k = 0; k < NBc; k++) { off[k] = a; a += cnt[k]; }
    }
    __syncthreads();
    if (tid < NBc) {
        int o = off[tid];
        for (int i = 0; i < Sc; i++)
            if (sb[i] == tid) order[base + (o++)] = i;
    }
}

// ---------------- chunked LSH attention: 2 chunks per CTA, single pass, FFMA2 ----------------
#define ATTN_SMEM (2*192*DHc*4 + 2*192*4)   // 99840 B

__global__ void __launch_bounds__(128) attn_kernel(
    const float* __restrict__ qk, const float* __restrict__ v,
    const int* __restrict__ order, const int* __restrict__ buckets,
    float* __restrict__ oall, float* __restrict__ lall)
{
    extern __shared__ float smemf[];
    float* Ke = smemf;
    float* Ve = smemf + 192 * DHc;
    int*   be = (int*)(smemf + 2 * 192 * DHc);
    int*   pe = be + 192;

    const int blk = blockIdx.x;
    const int np = blk & 31;
    const int h  = (blk >> 5) & (Hc - 1);
    const int b  = (blk >> 9) & (Bc - 1);
    const int r  = blk >> 10;
    const size_t rbh = (((size_t)r * Bc + b) * Hc + h) * Sc;
    const int tid = threadIdx.x;

    for (int j = tid; j < 192; j += 128) {
        const int ci = j >> 6;
        const int chunk = (2 * np + ci + NCHc - 1) & (NCHc - 1);
        const int spos = chunk * Cc + (j & 63);
        const int pk = order[rbh + spos];
        const float* kr = qk + ((size_t)(b * Sc + pk)) * Dc + h * DHc;
        const float* vr = v  + ((size_t)(b * Sc + pk)) * Dc + h * DHc;
        float ss = 0.f;
        float tmp[DHc];
        #pragma unroll
        for (int d = 0; d < DHc; d++) { float x = kr[d]; tmp[d] = x; ss = fmaf(x, x, ss); }
        const float sc = 1.f / (sqrtf(ss) + 1e-6f);
        #pragma unroll
        for (int d = 0; d < DHc; d++) { Ke[j * DHc + d] = tmp[d] * sc; Ve[j * DHc + d] = vr[d]; }
        be[j] = buckets[rbh + pk];
        pe[j] = pk;
    }
    __syncthreads();

    const int qc = tid >> 6;
    const int qi = tid & 63;
    const int curb  = 64 + qc * 64;
    const int prevb = qc * 64;
    const int self  = curb + qi;
    const int p  = pe[self];
    const int bq = be[self];

    unsigned long long q2[32];
    {
        const float* qr = qk + ((size_t)(b * Sc + p)) * Dc + h * DHc;
        const unsigned long long* q8 = (const unsigned long long*)qr;
        #pragma unroll
        for (int i = 0; i < 32; i++) q2[i] = q8[i];
    }

    unsigned long long acc2[32];
    #pragma unroll
    for (int i = 0; i < 32; i++) acc2[i] = 0ull;
    float sum = 0.f;

    #pragma unroll 1
    for (int seg = 0; seg < 2; seg++) {
        const int base = seg ? prevb : curb;
        #pragma unroll 1
        for (int jj = 0; jj < Cc; jj++) {
            const int j = base + jj;
            const ulonglong2* k4 = (const ulonglong2*)(Ke + j * DHc);
            unsigned long long sA = 0, sB = 0, sC = 0, sD = 0;
            #pragma unroll
            for (int i = 0; i < 8; i++) {
                ulonglong2 k0 = k4[2 * i];
                ulonglong2 k1 = k4[2 * i + 1];
                sA = f32x2_fma(q2[4 * i + 0], k0.x, sA);
                sB = f32x2_fma(q2[4 * i + 1], k0.y, sB);
                sC = f32x2_fma(q2[4 * i + 2], k1.x, sC);
                sD = f32x2_fma(q2[4 * i + 3], k1.y, sD);
            }
            float a0, a1, b0, b1, c0, c1, d0, d1;
            f32x2_unpack(sA, a0, a1); f32x2_unpack(sB, b0, b1);
            f32x2_unpack(sC, c0, c1); f32x2_unpack(sD, d0, d1);
            float s = (((a0 + a1) + (b0 + b1)) + ((c0 + c1) + (d0 + d1))) * 0.125f;
            if (bq != be[j]) s = -1e9f;
            if (p == pe[j])  s = -1e5f;
            const float e = __expf(s);
            sum += e;
            const unsigned long long e2 = f32x2_pack(e, e);
            const ulonglong2* v4 = (const ulonglong2*)(Ve + j * DHc);
            #pragma unroll
            for (int i = 0; i < 16; i++) {
                ulonglong2 vv = v4[i];
                acc2[2 * i + 0] = f32x2_fma(e2, vv.x, acc2[2 * i + 0]);
                acc2[2 * i + 1] = f32x2_fma(e2, vv.y, acc2[2 * i + 1]);
            }
        }
    }

    float* orow = oall + (rbh + p) * DHc;
    if (sum > 0.f) {
        const float linv = 1.f / sum;
        const unsigned long long l2 = f32x2_pack(linv, linv);
        unsigned long long* o8 = (unsigned long long*)orow;
        #pragma unroll
        for (int i = 0; i < 32; i++) o8[i] = f32x2_mul(acc2[i], l2);
        lall[rbh + p] = logf(sum);
    } else {
        const float* vs = Ve + self * DHc;
        #pragma unroll
        for (int d = 0; d < DHc; d++) orow[d] = vs[d];
        lall[rbh + p] = -1e5f;
    }
}

// ---------------- combine rounds -> fp16 output ----------------
__global__ void combine_kernel(const float* __restrict__ oall, const float* __restrict__ lall,
                               __half* __restrict__ out)
{
    const int t = blockIdx.x * blockDim.x + threadIdx.x;
    if (t >= BHS) return;
    const int s = t & (Sc - 1);
    const int h = (t >> 12) & (Hc - 1);
    const int b = t >> 16;
    const size_t idx = (size_t)t;
    const float l0 = lall[idx], l1 = lall[idx + BHS], l2 = lall[idx + 2 * (size_t)BHS], l3 = lall[idx + 3 * (size_t)BHS];
    const float m = fmaxf(fmaxf(l0, l1), fmaxf(l2, l3));
    float w0 = expf(l0 - m), w1 = expf(l1 - m), w2 = expf(l2 - m), w3 = expf(l3 - m);
    const float inv = 1.f / (w0 + w1 + w2 + w3);
    w0 *= inv; w1 *= inv; w2 *= inv; w3 *= inv;
    const float* o0 = oall + idx * DHc;
    const float* o1 = oall + (idx + BHS) * DHc;
    const float* o2 = oall + (idx + 2 * (size_t)BHS) * DHc;
    const float* o3 = oall + (idx + 3 * (size_t)BHS) * DHc;
    __half* dst = out + ((size_t)(b * Sc + s)) * Dc + h * DHc;
    #pragma unroll
    for (int d = 0; d < DHc; d++)
        dst[d] = __float2half_rn(w0 * o0[d] + w1 * o1[d] + w2 * o2[d] + w3 * o3[d]);
}

// ---------------- launch ----------------
extern "C" void kernel_launch(void* const* d_in, const int* in_sizes, int n_in,
                              void* d_out, int out_size)
{
    const float* x1    = (const float*)d_in[0];
    const float* x2    = (const float*)d_in[1];
    const float* Wqk   = (const float*)d_in[2];
    const float* Wv    = (const float*)d_in[3];
    const float* Wo    = (const float*)d_in[4];
    const float* ln1_g = (const float*)d_in[5];
    const float* ln1_b = (const float*)d_in[6];
    const float* W1    = (const float*)d_in[7];
    const float* bf1   = (const float*)d_in[8];
    const float* W2    = (const float*)d_in[9];
    const float* bf2   = (const float*)d_in[10];
    const float* ln2_g = (const float*)d_in[11];
    const float* ln2_b = (const float*)d_in[12];
    const float* rot   = (const float*)d_in[13];

    float *ln, *qk, *vv, *oall, *lall;
    __half *lnh, *attnh, *ffhh, *WvT, *WoT, *W1T, *W2T;
    int *bk, *ord;
    cudaGetSymbolAddress((void**)&ln,    g_ln);
    cudaGetSymbolAddress((void**)&lnh,   g_lnh);
    cudaGetSymbolAddress((void**)&qk,    g_qk);
    cudaGetSymbolAddress((void**)&vv,    g_v);
    cudaGetSymbolAddress((void**)&attnh, g_attnh);
    cudaGetSymbolAddress((void**)&ffhh,  g_ffhh);
    cudaGetSymbolAddress((void**)&oall,  g_oall);
    cudaGetSymbolAddress((void**)&lall,  g_lall);
    cudaGetSymbolAddress((void**)&bk,    g_buckets);
    cudaGetSymbolAddress((void**)&ord,   g_order);
    cudaGetSymbolAddress((void**)&WvT,   g_WvT);
    cudaGetSymbolAddress((void**)&WoT,   g_WoT);
    cudaGetSymbolAddress((void**)&W1T,   g_W1T);
    cudaGetSymbolAddress((void**)&W2T,   g_W2T);

    static cudaStream_t s2 = nullptr;
    static cudaEvent_t evT = nullptr, evF = nullptr, evJ = nullptr;
    if (!s2) {
        cudaStreamCreateWithFlags(&s2, cudaStreamNonBlocking);
        cudaEventCreateWithFlags(&evT, cudaEventDisableTiming);
        cudaEventCreateWithFlags(&evF, cudaEventDisableTiming);
        cudaEventCreateWithFlags(&evJ, cudaEventDisableTiming);
    }

    float* y1 = (float*)d_out;
    float* y2 = y1 + BSD;

    const int ROWS = Bc * Sc;   // 8192

    cudaFuncSetAttribute(hgemm_kernel, cudaFuncAttributeMaxDynamicSharedMemorySize, HGEMM_SMEM);
    cudaFuncSetAttribute(attn_kernel, cudaFuncAttributeMaxDynamicSharedMemorySize, ATTN_SMEM);

    // fork early: all weight transposes on s2 (independent of ln1)
    cudaEventRecord(evT, 0);
    cudaStreamWaitEvent(s2, evT, 0);
    transpose_half_kernel<<<dim3(Dc / 32,  Dc / 32),  256, 0, s2>>>(Wv, WvT, Dc,  Dc);
    transpose_half_kernel<<<dim3(Dc / 32,  Dc / 32),  256, 0, s2>>>(Wo, WoT, Dc,  Dc);
    transpose_half_kernel<<<dim3(DFFc / 32, Dc / 32), 256, 0, s2>>>(W1, W1T, Dc,  DFFc);
    transpose_half_kernel<<<dim3(Dc / 32, DFFc / 32), 256, 0, s2>>>(W2, W2T, DFFc, Dc);

    // ln1 on stream 0 (fp32 copy for exact qk; fp16 copy for v)
    ln_kernel<<<ROWS, 256>>>(x2, ln1_g, ln1_b, ln, lnh);
    cudaEventRecord(evF, 0);
    cudaStreamWaitEvent(s2, evF, 0);

    // v fp16 GEMM on s2 (after its transpose + ln1); qk chain on stream 0
    dim3 gD(Dc / 128, ROWS / 128);
    hgemm_kernel<<<gD, 256, HGEMM_SMEM, s2>>>(lnh, WvT, vv, nullptr, nullptr, nullptr, ROWS, Dc, Dc, 0);

    sgemm_kernel<<<gD, 256>>>(ln, Wqk, qk, ROWS, Dc, Dc);
    rotbucket_kernel<<<dim3(1, BHS / 128), 256>>>(qk, rot, bk, DHc);
    sort_kernel<<<Rc * Bc * Hc, 256>>>(bk, ord);

    cudaEventRecord(evJ, s2);
    cudaStreamWaitEvent(0, evJ, 0);

    attn_kernel<<<Rc * Bc * Hc * (NCHc / 2), 128, ATTN_SMEM>>>(qk, vv, ord, bk, oall, lall);

    combine_kernel<<<BHS / 256, 256>>>(oall, lall, attnh);

    hgemm_kernel<<<gD, 256, HGEMM_SMEM>>>(attnh, WoT, y1, nullptr, nullptr, x1, ROWS, Dc, Dc, 0);

    ln_kernel<<<ROWS, 256>>>(y1, ln2_g, ln2_b, nullptr, lnh);

    dim3 gF(DFFc / 128, ROWS / 128);
    hgemm_kernel<<<gF, 256, HGEMM_SMEM>>>(lnh, W1T, nullptr, ffhh, bf1, nullptr, ROWS, DFFc, Dc, 1);
    hgemm_kernel<<<gD, 256, HGEMM_SMEM>>>(ffhh, W2T, y2, nullptr, bf2, x2, ROWS, Dc, DFFc, 0);
}

// round 17
// speedup vs baseline: 1.3523x; 1.1860x over previous
#include <cuda_runtime.h>
#include <cuda_fp16.h>
#include <math.h>
#include <stdint.h>

// ---------------- problem dims ----------------
#define Bc   2
#define Sc   4096
#define Dc   1024
#define Hc   16
#define NBc  64
#define NB2c 32
#define Rc   4
#define DFFc 4096
#define DHc  64
#define Cc   64
#define NCHc 64
#define BHS  (Bc*Hc*Sc)          // 131072
#define BSD  ((size_t)Bc*Sc*Dc)  // 8388608

// ---------------- workspace (static device memory; no allocations) ----------------
__device__ float  g_ln[BSD];
__device__ __half g_lnh[BSD];
__device__ float  g_qk[BSD];
__device__ float  g_v[BSD];
__device__ __half g_attnh[BSD];
__device__ __half g_ffhh[(size_t)Bc*Sc*DFFc];
__device__ float  g_oall[(size_t)Rc*BHS*DHc];
__device__ float  g_lall[(size_t)Rc*BHS];
__device__ int    g_buckets[(size_t)Rc*BHS];
__device__ int    g_order[(size_t)Rc*BHS];
__device__ __half g_WvT[(size_t)Dc*Dc];
__device__ __half g_WoT[(size_t)Dc*Dc];
__device__ __half g_W1T[(size_t)DFFc*Dc];
__device__ __half g_W2T[(size_t)Dc*DFFc];

// ---------------- packed f32x2 helpers ----------------
__device__ __forceinline__ unsigned long long f32x2_pack(float lo, float hi) {
    unsigned long long r;
    asm("mov.b64 %0, {%1, %2};" : "=l"(r) : "f"(lo), "f"(hi));
    return r;
}
__device__ __forceinline__ unsigned long long f32x2_fma(unsigned long long a,
                                                        unsigned long long b,
                                                        unsigned long long c) {
    unsigned long long d;
    asm("fma.rn.f32x2 %0, %1, %2, %3;" : "=l"(d) : "l"(a), "l"(b), "l"(c));
    return d;
}
__device__ __forceinline__ unsigned long long f32x2_mul(unsigned long long a,
                                                        unsigned long long b) {
    unsigned long long d;
    asm("mul.rn.f32x2 %0, %1, %2;" : "=l"(d) : "l"(a), "l"(b));
    return d;
}
__device__ __forceinline__ void f32x2_unpack(unsigned long long v, float& lo, float& hi) {
    asm("mov.b64 {%0, %1}, %2;" : "=f"(lo), "=f"(hi) : "l"(v));
}

// ---------------- mma / cp.async / ldmatrix helpers ----------------
__device__ __forceinline__ void mma_f16(float c[4],
                                        uint32_t a0, uint32_t a1, uint32_t a2, uint32_t a3,
                                        uint32_t b0, uint32_t b1) {
    asm volatile(
        "mma.sync.aligned.m16n8k16.row.col.f32.f16.f16.f32 "
        "{%0,%1,%2,%3}, {%4,%5,%6,%7}, {%8,%9}, {%0,%1,%2,%3};"
        : "+f"(c[0]), "+f"(c[1]), "+f"(c[2]), "+f"(c[3])
        : "r"(a0), "r"(a1), "r"(a2), "r"(a3), "r"(b0), "r"(b1));
}
__device__ __forceinline__ uint32_t smem_u32(const void* p) {
    uint32_t a;
    asm("{ .reg .u64 t; cvta.to.shared.u64 t, %1; cvt.u32.u64 %0, t; }" : "=r"(a) : "l"(p));
    return a;
}
__device__ __forceinline__ void cp_async16(uint32_t dst, const void* src) {
    asm volatile("cp.async.ca.shared.global [%0], [%1], 16;" :: "r"(dst), "l"(src));
}
__device__ __forceinline__ void cp_commit() {
    asm volatile("cp.async.commit_group;" ::: "memory");
}
__device__ __forceinline__ void cp_wait1() {
    asm volatile("cp.async.wait_group 1;" ::: "memory");
}
__device__ __forceinline__ void ldsm_x4(uint32_t& r0, uint32_t& r1, uint32_t& r2, uint32_t& r3,
                                        uint32_t addr) {
    asm volatile("ldmatrix.sync.aligned.m8n8.x4.shared.b16 {%0,%1,%2,%3}, [%4];"
                 : "=r"(r0), "=r"(r1), "=r"(r2), "=r"(r3) : "r"(addr));
}

// ---------------- weight transpose to fp16 ----------------
__global__ void transpose_half_kernel(const float* __restrict__ W, __half* __restrict__ Wt,
                                      int K, int N)
{
    __shared__ float tile[32][33];
    const int bn = blockIdx.x * 32;
    const int bk = blockIdx.y * 32;
    const int tx = threadIdx.x & 31;
    const int ty = threadIdx.x >> 5;
    #pragma unroll
    for (int i = 0; i < 32; i += 8)
        tile[ty + i][tx] = W[(size_t)(bk + ty + i) * N + bn + tx];
    __syncthreads();
    #pragma unroll
    for (int i = 0; i < 32; i += 8)
        Wt[(size_t)(bn + ty + i) * K + bk + tx] = __float2half_rn(tile[tx][ty + i]);
}

// ---------------- layernorm (vectorized float4): fp32 (optional) + fp16 (optional) ----------------
__global__ void ln_kernel(const float* __restrict__ x, const float* __restrict__ g,
                          const float* __restrict__ bb, float* __restrict__ y,
                          __half* __restrict__ yh)
{
    const int row = blockIdx.x;
    const int tid = threadIdx.x;
    const float4 v = ((const float4*)(x + (size_t)row * Dc))[tid];
    float s1 = ((v.x + v.y) + (v.z + v.w));
    float s2 = fmaf(v.x, v.x, fmaf(v.y, v.y, fmaf(v.z, v.z, v.w * v.w)));

    __shared__ float sh1[8], sh2[8];
    const int lane = tid & 31, w = tid >> 5;
    #pragma unroll
    for (int o = 16; o > 0; o >>= 1) {
        s1 += __shfl_xor_sync(~0u, s1, o);
        s2 += __shfl_xor_sync(~0u, s2, o);
    }
    if (lane == 0) { sh1[w] = s1; sh2[w] = s2; }
    __syncthreads();
    if (w == 0) {
        s1 = (lane < 8) ? sh1[lane] : 0.f;
        s2 = (lane < 8) ? sh2[lane] : 0.f;
        #pragma unroll
        for (int o = 4; o > 0; o >>= 1) {
            s1 += __shfl_xor_sync(~0u, s1, o);
            s2 += __shfl_xor_sync(~0u, s2, o);
        }
        if (lane == 0) { sh1[0] = s1; sh2[0] = s2; }
    }
    __syncthreads();
    const float mean = sh1[0] * (1.f / Dc);
    const float var  = sh2[0] * (1.f / Dc) - mean * mean;
    const float inv  = 1.f / sqrtf(var + 1e-5f);

    const float4 gg = ((const float4*)g)[tid];
    const float4 b4 = ((const float4*)bb)[tid];
    float4 o;
    o.x = (v.x - mean) * inv * gg.x + b4.x;
    o.y = (v.y - mean) * inv * gg.y + b4.y;
    o.z = (v.z - mean) * inv * gg.z + b4.z;
    o.w = (v.w - mean) * inv * gg.w + b4.w;
    if (y) ((float4*)(y + (size_t)row * Dc))[tid] = o;
    if (yh) {
        __half2 h0 = __floats2half2_rn(o.x, o.y);
        __half2 h1 = __floats2half2_rn(o.z, o.w);
        uint32_t u0, u1;
        u0 = *(uint32_t*)&h0; u1 = *(uint32_t*)&h1;
        ((uint2*)(yh + (size_t)row * Dc))[tid] = make_uint2(u0, u1);
    }
}

// ---------------- exact fp32 SGEMM (FFMA2), k-tile 16: qk projection ----------------
__global__ void __launch_bounds__(256, 2) sgemm_kernel(
    const float* __restrict__ A, const float* __restrict__ Bm,
    float* __restrict__ Cm, int M, int N, int K)
{
    __shared__ float As[16][128];
    __shared__ float Bs[16][128];
    const int tid  = threadIdx.x;
    const int row0 = blockIdx.y * 128;
    const int col0 = blockIdx.x * 128;
    const int tx = tid & 15;
    const int ty = tid >> 4;

    const int aRow = tid >> 1;
    const int aCol = (tid & 1) << 3;
    const int bRow = tid >> 4;
    const int bCol = (tid & 15) << 3;

    const float* Aptr = A + (size_t)(row0 + aRow) * K + aCol;
    const float* Bptr = Bm + (size_t)bRow * N + col0 + bCol;

    unsigned long long acc2[8][4];
    #pragma unroll
    for (int i = 0; i < 8; i++)
        #pragma unroll
        for (int j = 0; j < 4; j++) acc2[i][j] = 0ull;

    float4 a4[2], b4[2];
    a4[0] = *(const float4*)(Aptr);
    a4[1] = *(const float4*)(Aptr + 4);
    b4[0] = *(const float4*)(Bptr);
    b4[1] = *(const float4*)(Bptr + 4);

    for (int k0 = 0; k0 < K; k0 += 16) {
        #pragma unroll
        for (int q = 0; q < 2; q++) {
            As[aCol + q * 4 + 0][aRow] = a4[q].x;
            As[aCol + q * 4 + 1][aRow] = a4[q].y;
            As[aCol + q * 4 + 2][aRow] = a4[q].z;
            As[aCol + q * 4 + 3][aRow] = a4[q].w;
        }
        *(float4*)(&Bs[bRow][bCol])     = b4[0];
        *(float4*)(&Bs[bRow][bCol + 4]) = b4[1];
        __syncthreads();

        if (k0 + 16 < K) {
            a4[0] = *(const float4*)(Aptr + k0 + 16);
            a4[1] = *(const float4*)(Aptr + k0 + 20);
            b4[0] = *(const float4*)(Bptr + (size_t)(k0 + 16) * N);
            b4[1] = *(const float4*)(Bptr + (size_t)(k0 + 16) * N + 4);
        }

        #pragma unroll
        for (int k = 0; k < 16; k++) {
            float4 a0 = *(const float4*)(&As[k][ty * 4]);
            float4 a1 = *(const float4*)(&As[k][64 + ty * 4]);
            unsigned long long b2[4];
            const ulonglong2* bp0 = (const ulonglong2*)(&Bs[k][tx * 4]);
            ulonglong2 bl = bp0[0];
            b2[0] = bl.x; b2[1] = bl.y;
            const ulonglong2* bp1 = (const ulonglong2*)(&Bs[k][64 + tx * 4]);
            ulonglong2 bh = bp1[0];
            b2[2] = bh.x; b2[3] = bh.y;
            float av[8] = {a0.x, a0.y, a0.z, a0.w, a1.x, a1.y, a1.z, a1.w};
            #pragma unroll
            for (int i = 0; i < 8; i++) {
                const unsigned long long ad = f32x2_pack(av[i], av[i]);
                #pragma unroll
                for (int j = 0; j < 4; j++)
                    acc2[i][j] = f32x2_fma(ad, b2[j], acc2[i][j]);
            }
        }
        __syncthreads();
    }

    #pragma unroll
    for (int i = 0; i < 8; i++) {
        const int m = row0 + ((i < 4) ? (ty * 4 + i) : (64 + ty * 4 + i - 4));
        #pragma unroll
        for (int j = 0; j < 4; j++) {
            const int n = col0 + ((j < 2) ? (tx * 4 + j * 2) : (64 + tx * 4 + (j - 2) * 2));
            float lo, hi;
            f32x2_unpack(acc2[i][j], lo, hi);
            *(float2*)(&Cm[(size_t)m * N + n]) = make_float2(lo, hi);
        }
    }
}

// ---------------- fused rotation-GEMM + per-round argmax -> buckets ----------------
__global__ void __launch_bounds__(256, 2) rotbucket_kernel(
    const float* __restrict__ A, const float* __restrict__ Bm,
    int* __restrict__ buckets, int K)
{
    __shared__ float As[8][128];
    __shared__ float Bs[8][128];
    const int tid  = threadIdx.x;
    const int row0 = blockIdx.y * 128;
    const int tx = tid & 15;
    const int ty = tid >> 4;

    const int aRow = tid >> 1;
    const int aCol = (tid & 1) << 2;
    const int bRow = tid >> 5;
    const int bCol = (tid & 31) << 2;

    const float* Aptr = A + (size_t)(row0 + aRow) * K + aCol;
    const float* Bptr = Bm + (size_t)bRow * 128 + bCol;

    unsigned long long acc2[8][4];
    #pragma unroll
    for (int i = 0; i < 8; i++)
        #pragma unroll
        for (int j = 0; j < 4; j++) acc2[i][j] = 0ull;

    float4 a4 = *(const float4*)(Aptr);
    float4 b4 = *(const float4*)(Bptr);

    for (int k0 = 0; k0 < K; k0 += 8) {
        As[aCol + 0][aRow] = a4.x;
        As[aCol + 1][aRow] = a4.y;
        As[aCol + 2][aRow] = a4.z;
        As[aCol + 3][aRow] = a4.w;
        *(float4*)(&Bs[bRow][bCol]) = b4;
        __syncthreads();

        if (k0 + 8 < K) {
            a4 = *(const float4*)(Aptr + k0 + 8);
            b4 = *(const float4*)(Bptr + (size_t)(k0 + 8) * 128);
        }

        #pragma unroll
        for (int k = 0; k < 8; k++) {
            float4 a0 = *(const float4*)(&As[k][ty * 4]);
            float4 a1 = *(const float4*)(&As[k][64 + ty * 4]);
            unsigned long long b2[4];
            const unsigned long long* bp0 = (const unsigned long long*)(&Bs[k][tx * 4]);
            b2[0] = bp0[0];
            b2[1] = bp0[1];
            const unsigned long long* bp1 = (const unsigned long long*)(&Bs[k][64 + tx * 4]);
            b2[2] = bp1[0];
            b2[3] = bp1[1];
            float av[8] = {a0.x, a0.y, a0.z, a0.w, a1.x, a1.y, a1.z, a1.w};
            #pragma unroll
            for (int i = 0; i < 8; i++) {
                const unsigned long long ad = f32x2_pack(av[i], av[i]);
                #pragma unroll
                for (int j = 0; j < 4; j++)
                    acc2[i][j] = f32x2_fma(ad, b2[j], acc2[i][j]);
            }
        }
        __syncthreads();
    }

    const int txg = tx & 7;
    const int rA  = tx >> 3;
    #pragma unroll
    for (int i = 0; i < 8; i++) {
        const int m = row0 + ((i < 4) ? (ty * 4 + i) : (64 + ty * 4 + i - 4));
        #pragma unroll
        for (int half = 0; half < 2; half++) {
            float bv = -1e30f; int bi = 0;
            #pragma unroll
            for (int j = 0; j < 2; j++) {
                const int k = 4 * txg + j * 2;
                float lo, hi;
                f32x2_unpack(acc2[i][half * 2 + j], lo, hi);
                if (lo  > bv || (lo  == bv && k < bi))        { bv = lo;  bi = k; }
                if (hi  > bv || (hi  == bv && k + 1 < bi))    { bv = hi;  bi = k + 1; }
                if (-lo > bv || (-lo == bv && 32 + k < bi))   { bv = -lo; bi = 32 + k; }
                if (-hi > bv || (-hi == bv && 33 + k < bi))   { bv = -hi; bi = 33 + k; }
            }
            #pragma unroll
            for (int o = 1; o < 8; o <<= 1) {
                const float ov = __shfl_xor_sync(0xffffffffu, bv, o);
                const int   oi = __shfl_xor_sync(0xffffffffu, bi, o);
                if (ov > bv || (ov == bv && oi < bi)) { bv = ov; bi = oi; }
            }
            if (txg == 0) {
                const int r  = rA + half * 2;
                const int hh = m & (Hc - 1);
                const int ss = (m >> 4) & (Sc - 1);
                const int bb = m >> 16;
                buckets[(size_t)r * BHS + bb * (Hc * Sc) + hh * Sc + ss] = bi;
            }
        }
    }
}

// ---------------- fp16 tensor-core GEMM (m16n8k16), fp32 accum, k-tile 64 ----------------
#define TSH 72
#define HGEMM_SMEM (4*128*TSH*2)      // 73728 B

__global__ void __launch_bounds__(256, 2) hgemm_kernel(
    const __half* __restrict__ A, const __half* __restrict__ Bt,
    float* __restrict__ Cm, __half* __restrict__ Ch,
    const float* __restrict__ bias, const float* __restrict__ add,
    int M, int N, int K, int relu)
{
    extern __shared__ __half smh[];
    const uint32_t sb = smem_u32(smh);
    const uint32_t BUFSZ = 2 * 128 * TSH * 2;
    const uint32_t BOFFS = 128 * TSH * 2;

    const int tid  = threadIdx.x;
    const int lane = tid & 31;
    const int warp = tid >> 5;
    const int wm = warp >> 2;
    const int wn = warp & 3;
    const int row0 = blockIdx.y * 128;
    const int col0 = blockIdx.x * 128;

    const int r  = tid >> 1;
    const int hf = tid & 1;
    const __half* Ag = A  + (size_t)(row0 + r) * K + hf * 32;
    const __half* Bg = Bt + (size_t)(col0 + r) * K + hf * 32;
    const uint32_t adst0 = sb + (uint32_t)(r * TSH + hf * 32) * 2;
    const uint32_t bdst0 = adst0 + BOFFS;

    const int lm   = lane >> 3;
    const int lrow = (lm & 1) * 8 + (lane & 7);
    const int lkh  = lm >> 1;
    const uint32_t a_frag0 = sb + (uint32_t)((wm * 64 + lrow) * TSH) * 2 + lkh * 16;
    const int brow2 = ((lane >> 4) & 1) * 8 + (lane & 7);
    const int bkh   = (lane >> 3) & 1;
    const uint32_t b_frag0 = sb + BOFFS + (uint32_t)((wn * 32 + brow2) * TSH) * 2 + bkh * 16;

    float acc[4][4][4];
    #pragma unroll
    for (int mi = 0; mi < 4; mi++)
        #pragma unroll
        for (int ni = 0; ni < 4; ni++)
            #pragma unroll
            for (int c = 0; c < 4; c++) acc[mi][ni][c] = 0.f;

    const int T = K >> 6;

    #pragma unroll
    for (int i = 0; i < 4; i++) cp_async16(adst0 + i * 16, Ag + i * 8);
    #pragma unroll
    for (int i = 0; i < 4; i++) cp_async16(bdst0 + i * 16, Bg + i * 8);
    cp_commit();

    for (int t = 0; t < T; t++) {
        const int buf = t & 1;
        if (t + 1 < T) {
            const uint32_t ad = adst0 + (buf ^ 1) * BUFSZ;
            const uint32_t bd = bdst0 + (buf ^ 1) * BUFSZ;
            const __half* asrc = Ag + (t + 1) * 64;
            const __half* bsrc = Bg + (t + 1) * 64;
            #pragma unroll
            for (int i = 0; i < 4; i++) cp_async16(ad + i * 16, asrc + i * 8);
            #pragma unroll
            for (int i = 0; i < 4; i++) cp_async16(bd + i * 16, bsrc + i * 8);
        }
        cp_commit();
        cp_wait1();
        __syncthreads();

        const uint32_t abase = a_frag0 + buf * BUFSZ;
        const uint32_t bbase = b_frag0 + buf * BUFSZ;

        #pragma unroll
        for (int ks = 0; ks < 4; ks++) {
            uint32_t af[4][4];
            #pragma unroll
            for (int mi = 0; mi < 4; mi++)
                ldsm_x4(af[mi][0], af[mi][1], af[mi][2], af[mi][3],
                        abase + mi * (16 * TSH * 2) + ks * 32);
            uint32_t bf[4][2];
            #pragma unroll
            for (int p = 0; p < 2; p++)
                ldsm_x4(bf[2 * p][0], bf[2 * p][1], bf[2 * p + 1][0], bf[2 * p + 1][1],
                        bbase + p * (16 * TSH * 2) + ks * 32);
            #pragma unroll
            for (int mi = 0; mi < 4; mi++)
                #pragma unroll
                for (int ni = 0; ni < 4; ni++)
                    mma_f16(acc[mi][ni], af[mi][0], af[mi][1], af[mi][2], af[mi][3],
                            bf[ni][0], bf[ni][1]);
        }
        __syncthreads();
    }

    #pragma unroll
    for (int mi = 0; mi < 4; mi++) {
        #pragma unroll
        for (int ni = 0; ni < 4; ni++) {
            const int m = row0 + wm * 64 + mi * 16 + (lane >> 2);
            const int n = col0 + wn * 32 + ni * 8 + (lane & 3) * 2;
            float c0 = acc[mi][ni][0], c1 = acc[mi][ni][1];
            float c2 = acc[mi][ni][2], c3 = acc[mi][ni][3];
            if (bias) {
                const float b0 = __ldg(&bias[n]), b1 = __ldg(&bias[n + 1]);
                c0 += b0; c1 += b1; c2 += b0; c3 += b1;
            }
            if (add) {
                c0 += __ldg(&add[(size_t)m * N + n]);
                c1 += __ldg(&add[(size_t)m * N + n + 1]);
                c2 += __ldg(&add[(size_t)(m + 8) * N + n]);
                c3 += __ldg(&add[(size_t)(m + 8) * N + n + 1]);
            }
            if (relu) {
                c0 = fmaxf(c0, 0.f); c1 = fmaxf(c1, 0.f);
                c2 = fmaxf(c2, 0.f); c3 = fmaxf(c3, 0.f);
            }
            if (Ch) {
                *(__half2*)(&Ch[(size_t)m * N + n]) = __floats2half2_rn(c0, c1);
                *(__half2*)(&Ch[(size_t)(m + 8) * N + n]) = __floats2half2_rn(c2, c3);
            } else {
                *(float2*)(&Cm[(size_t)m * N + n]) = make_float2(c0, c1);
                *(float2*)(&Cm[(size_t)(m + 8) * N + n]) = make_float2(c2, c3);
            }
        }
    }
}

// ---------------- stable counting sort per (r,b,h) ----------------
__global__ void sort_kernel(const int* __restrict__ buckets, int* __restrict__ order)
{
    __shared__ int sb[Sc];
    __shared__ int cnt[NBc];
    __shared__ int off[NBc];
    const size_t base = (size_t)blockIdx.x * Sc;
    const int tid = threadIdx.x;
    if (tid < NBc) cnt[tid] = 0;
    __syncthreads();
    for (int i = tid; i < Sc; i += blockDim.x) {
        int bk = buckets[base + i];
        sb[i] = bk;
        atomicAdd(&cnt[bk], 1);
    }
    __syncthreads();
    if (tid == 0) {
        int a = 0;
        for (int k = 0; k < NBc; k++) { off[k] = a; a += cnt[k]; }
    }
    __syncthreads();
    if (tid < NBc) {
        int o = off[tid];
        for (int i = 0; i < Sc; i++)
            if (sb[i] == tid) order[base + (o++)] = i;
    }
}

// ---------------- chunked LSH attention: 2 chunks per CTA, single pass, FFMA2 ----------------
// staging now fully vectorized (float4 gathers; rows are 256B-aligned by construction)
#define ATTN_SMEM (2*192*DHc*4 + 2*192*4)   // 99840 B

__global__ void __launch_bounds__(128) attn_kernel(
    const float* __restrict__ qk, const float* __restrict__ v,
    const int* __restrict__ order, const int* __restrict__ buckets,
    float* __restrict__ oall, float* __restrict__ lall)
{
    extern __shared__ float smemf[];
    float* Ke = smemf;
    float* Ve = smemf + 192 * DHc;
    int*   be = (int*)(smemf + 2 * 192 * DHc);
    int*   pe = be + 192;

    const int blk = blockIdx.x;
    const int np = blk & 31;
    const int h  = (blk >> 5) & (Hc - 1);
    const int b  = (blk >> 9) & (Bc - 1);
    const int r  = blk >> 10;
    const size_t rbh = (((size_t)r * Bc + b) * Hc + h) * Sc;
    const int tid = threadIdx.x;

    for (int j = tid; j < 192; j += 128) {
        const int ci = j >> 6;
        const int chunk = (2 * np + ci + NCHc - 1) & (NCHc - 1);
        const int spos = chunk * Cc + (j & 63);
        const int pk = order[rbh + spos];
        const float4* kr4 = (const float4*)(qk + ((size_t)(b * Sc + pk)) * Dc + h * DHc);
        const float4* vr4 = (const float4*)(v  + ((size_t)(b * Sc + pk)) * Dc + h * DHc);
        float4 kk[16];
        float s0 = 0.f, s1 = 0.f, s2 = 0.f, s3 = 0.f;
        #pragma unroll
        for (int i = 0; i < 16; i++) {
            kk[i] = kr4[i];
            s0 = fmaf(kk[i].x, kk[i].x, s0);
            s1 = fmaf(kk[i].y, kk[i].y, s1);
            s2 = fmaf(kk[i].z, kk[i].z, s2);
            s3 = fmaf(kk[i].w, kk[i].w, s3);
        }
        const float ss = (s0 + s1) + (s2 + s3);
        const float sc = 1.f / (sqrtf(ss) + 1e-6f);
        float4* kedst = (float4*)(Ke + j * DHc);
        float4* vedst = (float4*)(Ve + j * DHc);
        #pragma unroll
        for (int i = 0; i < 16; i++) {
            float4 ko;
            ko.x = kk[i].x * sc; ko.y = kk[i].y * sc;
            ko.z = kk[i].z * sc; ko.w = kk[i].w * sc;
            kedst[i] = ko;
            vedst[i] = vr4[i];
        }
        be[j] = buckets[rbh + pk];
        pe[j] = pk;
    }
    __syncthreads();

    const int qc = tid >> 6;
    const int qi = tid & 63;
    const int curb  = 64 + qc * 64;
    const int prevb = qc * 64;
    const int self  = curb + qi;
    const int p  = pe[self];
    const int bq = be[self];

    unsigned long long q2[32];
    {
        const float* qr = qk + ((size_t)(b * Sc + p)) * Dc + h * DHc;
        const unsigned long long* q8 = (const unsigned long long*)qr;
        #pragma unroll
        for (int i = 0; i < 32; i++) q2[i] = q8[i];
    }

    unsigned long long acc2[32];
    #pragma unroll
    for (int i = 0; i < 32; i++) acc2[i] = 0ull;
    float sum = 0.f;

    #pragma unroll 1
    for (int seg = 0; seg < 2; seg++) {
        const int base = seg ? prevb : curb;
        #pragma unroll 1
        for (int jj = 0; jj < Cc; jj++) {
            const int j = base + jj;
            const ulonglong2* k4 = (const ulonglong2*)(Ke + j * DHc);
            unsigned long long sA = 0, sB = 0, sC = 0, sD = 0;
            #pragma unroll
            for (int i = 0; i < 8; i++) {
                ulonglong2 k0 = k4[2 * i];
                ulonglong2 k1 = k4[2 * i + 1];
                sA = f32x2_fma(q2[4 * i + 0], k0.x, sA);
                sB = f32x2_fma(q2[4 * i + 1], k0.y, sB);
                sC = f32x2_fma(q2[4 * i + 2], k1.x, sC);
                sD = f32x2_fma(q2[4 * i + 3], k1.y, sD);
            }
            float a0, a1, b0, b1, c0, c1, d0, d1;
            f32x2_unpack(sA, a0, a1); f32x2_unpack(sB, b0, b1);
            f32x2_unpack(sC, c0, c1); f32x2_unpack(sD, d0, d1);
            float s = (((a0 + a1) + (b0 + b1)) + ((c0 + c1) + (d0 + d1))) * 0.125f;
            if (bq != be[j]) s = -1e9f;
            if (p == pe[j])  s = -1e5f;
            const float e = __expf(s);
            sum += e;
            const unsigned long long e2 = f32x2_pack(e, e);
            const ulonglong2* v4 = (const ulonglong2*)(Ve + j * DHc);
            #pragma unroll
            for (int i = 0; i < 16; i++) {
                ulonglong2 vv = v4[i];
                acc2[2 * i + 0] = f32x2_fma(e2, vv.x, acc2[2 * i + 0]);
                acc2[2 * i + 1] = f32x2_fma(e2, vv.y, acc2[2 * i + 1]);
            }
        }
    }

    float* orow = oall + (rbh + p) * DHc;
    if (sum > 0.f) {
        const float linv = 1.f / sum;
        const unsigned long long l2 = f32x2_pack(linv, linv);
        unsigned long long* o8 = (unsigned long long*)orow;
        #pragma unroll
        for (int i = 0; i < 32; i++) o8[i] = f32x2_mul(acc2[i], l2);
        lall[rbh + p] = logf(sum);
    } else {
        const float* vs = Ve + self * DHc;
        #pragma unroll
        for (int d = 0; d < DHc; d++) orow[d] = vs[d];
        lall[rbh + p] = -1e5f;
    }
}

// ---------------- combine rounds -> fp16 output (vectorized) ----------------
__global__ void combine_kernel(const float* __restrict__ oall, const float* __restrict__ lall,
                               __half* __restrict__ out)
{
    const int t = blockIdx.x * blockDim.x + threadIdx.x;
    if (t >= BHS) return;
    const int s = t & (Sc - 1);
    const int h = (t >> 12) & (Hc - 1);
    const int b = t >> 16;
    const size_t idx = (size_t)t;
    const float l0 = lall[idx], l1 = lall[idx + BHS], l2 = lall[idx + 2 * (size_t)BHS], l3 = lall[idx + 3 * (size_t)BHS];
    const float m = fmaxf(fmaxf(l0, l1), fmaxf(l2, l3));
    float w0 = expf(l0 - m), w1 = expf(l1 - m), w2 = expf(l2 - m), w3 = expf(l3 - m);
    const float inv = 1.f / (w0 + w1 + w2 + w3);
    w0 *= inv; w1 *= inv; w2 *= inv; w3 *= inv;
    const float4* o0 = (const float4*)(oall + idx * DHc);
    const float4* o1 = (const float4*)(oall + (idx + BHS) * DHc);
    const float4* o2 = (const float4*)(oall + (idx + 2 * (size_t)BHS) * DHc);
    const float4* o3 = (const float4*)(oall + (idx + 3 * (size_t)BHS) * DHc);
    __half* dst = out + ((size_t)(b * Sc + s)) * Dc + h * DHc;
    #pragma unroll
    for (int i = 0; i < 16; i++) {
        const float4 a = o0[i], bb4 = o1[i], c = o2[i], e = o3[i];
        float rx = w0 * a.x + w1 * bb4.x + w2 * c.x + w3 * e.x;
        float ry = w0 * a.y + w1 * bb4.y + w2 * c.y + w3 * e.y;
        float rz = w0 * a.z + w1 * bb4.z + w2 * c.z + w3 * e.z;
        float rw = w0 * a.w + w1 * bb4.w + w2 * c.w + w3 * e.w;
        __half2 h0 = __floats2half2_rn(rx, ry);
        __half2 h1 = __floats2half2_rn(rz, rw);
        uint32_t u0 = *(uint32_t*)&h0, u1 = *(uint32_t*)&h1;
        ((uint2*)dst)[i] = make_uint2(u0, u1);
    }
}

// ---------------- launch ----------------
extern "C" void kernel_launch(void* const* d_in, const int* in_sizes, int n_in,
                              void* d_out, int out_size)
{
    const float* x1    = (const float*)d_in[0];
    const float* x2    = (const float*)d_in[1];
    const float* Wqk   = (const float*)d_in[2];
    const float* Wv    = (const float*)d_in[3];
    const float* Wo    = (const float*)d_in[4];
    const float* ln1_g = (const float*)d_in[5];
    const float* ln1_b = (const float*)d_in[6];
    const float* W1    = (const float*)d_in[7];
    const float* bf1   = (const float*)d_in[8];
    const float* W2    = (const float*)d_in[9];
    const float* bf2   = (const float*)d_in[10];
    const float* ln2_g = (const float*)d_in[11];
    const float* ln2_b = (const float*)d_in[12];
    const float* rot   = (const float*)d_in[13];

    float *ln, *qk, *vv, *oall, *lall;
    __half *lnh, *attnh, *ffhh, *WvT, *WoT, *W1T, *W2T;
    int *bk, *ord;
    cudaGetSymbolAddress((void**)&ln,    g_ln);
    cudaGetSymbolAddress((void**)&lnh,   g_lnh);
    cudaGetSymbolAddress((void**)&qk,    g_qk);
    cudaGetSymbolAddress((void**)&vv,    g_v);
    cudaGetSymbolAddress((void**)&attnh, g_attnh);
    cudaGetSymbolAddress((void**)&ffhh,  g_ffhh);
    cudaGetSymbolAddress((void**)&oall,  g_oall);
    cudaGetSymbolAddress((void**)&lall,  g_lall);
    cudaGetSymbolAddress((void**)&bk,    g_buckets);
    cudaGetSymbolAddress((void**)&ord,   g_order);
    cudaGetSymbolAddress((void**)&WvT,   g_WvT);
    cudaGetSymbolAddress((void**)&WoT,   g_WoT);
    cudaGetSymbolAddress((void**)&W1T,   g_W1T);
    cudaGetSymbolAddress((void**)&W2T,   g_W2T);

    static cudaStream_t s2 = nullptr;
    static cudaEvent_t evT = nullptr, evF = nullptr, evJ = nullptr;
    if (!s2) {
        cudaStreamCreateWithFlags(&s2, cudaStreamNonBlocking);
        cudaEventCreateWithFlags(&evT, cudaEventDisableTiming);
        cudaEventCreateWithFlags(&evF, cudaEventDisableTiming);
        cudaEventCreateWithFlags(&evJ, cudaEventDisableTiming);
    }

    float* y1 = (float*)d_out;
    float* y2 = y1 + BSD;

    const int ROWS = Bc * Sc;   // 8192

    cudaFuncSetAttribute(hgemm_kernel, cudaFuncAttributeMaxDynamicSharedMemorySize, HGEMM_SMEM);
    cudaFuncSetAttribute(attn_kernel, cudaFuncAttributeMaxDynamicSharedMemorySize, ATTN_SMEM);

    // fork early: all weight transposes on s2 (independent of ln1)
    cudaEventRecord(evT, 0);
    cudaStreamWaitEvent(s2, evT, 0);
    transpose_half_kernel<<<dim3(Dc / 32,  Dc / 32),  256, 0, s2>>>(Wv, WvT, Dc,  Dc);
    transpose_half_kernel<<<dim3(Dc / 32,  Dc / 32),  256, 0, s2>>>(Wo, WoT, Dc,  Dc);
    transpose_half_kernel<<<dim3(DFFc / 32, Dc / 32), 256, 0, s2>>>(W1, W1T, Dc,  DFFc);
    transpose_half_kernel<<<dim3(Dc / 32, DFFc / 32), 256, 0, s2>>>(W2, W2T, DFFc, Dc);

    // ln1 on stream 0 (fp32 copy for exact qk; fp16 copy for v)
    ln_kernel<<<ROWS, 256>>>(x2, ln1_g, ln1_b, ln, lnh);
    cudaEventRecord(evF, 0);
    cudaStreamWaitEvent(s2, evF, 0);

    // v fp16 GEMM on s2 (after its transpose + ln1); qk chain on stream 0
    dim3 gD(Dc / 128, ROWS / 128);
    hgemm_kernel<<<gD, 256, HGEMM_SMEM, s2>>>(lnh, WvT, vv, nullptr, nullptr, nullptr, ROWS, Dc, Dc, 0);

    sgemm_kernel<<<gD, 256>>>(ln, Wqk, qk, ROWS, Dc, Dc);
    rotbucket_kernel<<<dim3(1, BHS / 128), 256>>>(qk, rot, bk, DHc);
    sort_kernel<<<Rc * Bc * Hc, 256>>>(bk, ord);

    cudaEventRecord(evJ, s2);
    cudaStreamWaitEvent(0, evJ, 0);

    attn_kernel<<<Rc * Bc * Hc * (NCHc / 2), 128, ATTN_SMEM>>>(qk, vv, ord, bk, oall, lall);

    combine_kernel<<<BHS / 256, 256>>>(oall, lall, attnh);

    hgemm_kernel<<<gD, 256, HGEMM_SMEM>>>(attnh, WoT, y1, nullptr, nullptr, x1, ROWS, Dc, Dc, 0);

    ln_kernel<<<ROWS, 256>>>(y1, ln2_g, ln2_b, nullptr, lnh);

    dim3 gF(DFFc / 128, ROWS / 128);
    hgemm_kernel<<<gF, 256, HGEMM_SMEM>>>(lnh, W1T, nullptr, ffhh, bf1, nullptr, ROWS, DFFc, Dc, 1);
    hgemm_kernel<<<gD, 256, HGEMM_SMEM>>>(ffhh, W2T, y2, nullptr, bf2, x2, ROWS, Dc, DFFc, 0);
}